// round 13
// baseline (speedup 1.0000x reference)
#include <cuda_runtime.h>
#include <math_constants.h>

#define NTOK  2048
#define FFN   2048

// ---------------- scratch ----------------
__device__ float g_xr  [NTOK * 1024];
__device__ float g_q   [NTOK * 1024];
__device__ float g_kt  [2 * 1024 * 1024];
__device__ float g_v   [NTOK * 1024];
__device__ float g_gate[NTOK * 1024];
__device__ float g_s   [(size_t)2 * 16 * 1024 * 1024];
__device__ float g_ps  [32 * 1024 * 8];          // per-(b,h,q) exp-sum partials
__device__ float g_o   [NTOK * 1024];
__device__ float g_r1  [NTOK * 1024];
__device__ float g_y   [NTOK * 1024];
__device__ float g_u   [NTOK * FFN];
__device__ float g_r2  [NTOK * 1024];

enum { EPI_PROJ4 = 0, EPI_SCOREBIAS = 1, EPI_GATE = 2, EPI_RESBIAS = 3, EPI_SILU = 4 };

struct XArgs {
    const float* Bw1; const float* Bw2; const float* Bw3;  // wk, wv, wg
    float* Ckt; float* Cv; float* Cg;                      // kt, v, gate outputs
    const float* bg;                                       // gate bias
    const float* eb;                                       // edge bias [b,q,k,h]
    float* ps;                                             // exp-sum partials
    float* aout;                                           // attn_out [b,q,k,h]
};

__device__ __forceinline__ unsigned f2tf32(float f) {
    unsigned r;
    asm("cvt.rna.tf32.f32 %0, %1;" : "=r"(r) : "f"(f));
    return r;
}
__device__ __forceinline__ float frnd(float f) { return __uint_as_float(f2tf32(f)); }

__device__ __forceinline__ void cp16(unsigned dst, const void* src, bool pred) {
    int sz = pred ? 16 : 0;
    asm volatile("cp.async.cg.shared.global [%0], [%1], 16, %2;"
                 :: "r"(dst), "l"(src), "r"(sz));
}

__device__ __forceinline__ void mma_tf32(float* c, const unsigned* a, const unsigned* b) {
    asm volatile(
        "mma.sync.aligned.m16n8k8.row.col.f32.tf32.tf32.f32 "
        "{%0,%1,%2,%3}, {%4,%5,%6,%7}, {%8,%9}, {%0,%1,%2,%3};"
        : "+f"(c[0]), "+f"(c[1]), "+f"(c[2]), "+f"(c[3])
        : "r"(a[0]), "r"(a[1]), "r"(a[2]), "r"(a[3]), "r"(b[0]), "r"(b[1]));
}

// ====== R6-proven 2-stage cp.async TF32 GEMM, BK=32 ========================
template<int BN, int EPI, bool ZX, bool PEXP>
__global__ __launch_bounds__(256, 2)
void tgemm(const float* __restrict__ A, const float* __restrict__ B,
           float* __restrict__ C, int M, int N, int K,
           int lda, int ldb, int ldc, int zdiv,
           long long sA1, long long sA2, long long sB1, long long sB2,
           long long sC1, long long sC2,
           const float* __restrict__ bias, const float* __restrict__ res,
           const unsigned char* __restrict__ mask, XArgs xa)
{
    constexpr int BM = 128, BK = 32, AS = BK + 4, BS = BN + 8;
    constexpr int MT = 2;
    constexpr int NT = BN / 16;
    constexpr int WN = BN / 2;

    extern __shared__ float smem[];
    float* As_ = smem;
    float* Bs_ = smem + 2 * BM * AS;

    int z, bn, bm;
    if (ZX) { z = blockIdx.x; bn = blockIdx.y; bm = blockIdx.z; }
    else    { z = blockIdx.z; bn = blockIdx.x; bm = blockIdx.y; }
    int z1 = z / zdiv, z2 = z - z1 * zdiv;
    A += (size_t)z1 * sA1 + (size_t)z2 * sA2;
    size_t coff = (size_t)z1 * sC1 + (size_t)z2 * sC2;

    const float* Bbase = B;
    int bnoff = bn * BN;
    int bsel = 0;
    if (EPI == EPI_PROJ4) {
        bsel = bn >> 3;
        bnoff = (bn & 7) * 128;
        Bbase = (bsel == 0) ? B : (bsel == 1) ? xa.Bw1 : (bsel == 2) ? xa.Bw2 : xa.Bw3;
    } else {
        Bbase += (size_t)z1 * sB1 + (size_t)z2 * sB2;
    }

    int tid = threadIdx.x, lane = tid & 31, wid = tid >> 5;
    int wm = (wid & 3) * 32;
    int wn = (wid >> 2) * WN;

    float sinv = 0.f;
    float* aout_base = nullptr;
    int xrow = tid >> 1, xc0 = (tid & 1) * 16;
    if (PEXP) {
        int qg = bm * BM + xrow;
        const float* p8 = xa.ps + ((size_t)z * 1024 + qg) * 8;
        float sum = ((p8[0] + p8[1]) + (p8[2] + p8[3]))
                  + ((p8[4] + p8[5]) + (p8[6] + p8[7]));
        sinv = 1.f / sum;
        // attn_out[b][q][k][h]: base for k = xc0 (advance by kt*32*16 per tile)
        aout_base = xa.aout + (((size_t)(z1 * 1024 + qg)) * 1024 + xc0) * 16 + z2;
    }

    unsigned as_base = (unsigned)__cvta_generic_to_shared(As_);
    unsigned bs_base = (unsigned)__cvta_generic_to_shared(Bs_);

    const float* Ag = A + (size_t)(bm * BM) * lda;
    const float* Bg = Bbase + bnoff;

    float acc[MT][NT][4] = {};

    constexpr int ALD = (BM * BK) / (256 * 4);
    constexpr int BLD = (BK * BN) / (256 * 4);

    int KT = K / BK;

    {
#pragma unroll
        for (int i = 0; i < ALD; i++) {
            int f = tid + 256 * i;
            int row = f >> 3, c4 = (f & 7) * 4;
            cp16(as_base + (unsigned)(row * AS + c4) * 4,
                 Ag + (size_t)row * lda + c4, true);
        }
#pragma unroll
        for (int i = 0; i < BLD; i++) {
            int f = tid + 256 * i;
            int row = f / (BN / 4), c4 = (f % (BN / 4)) * 4;
            cp16(bs_base + (unsigned)(row * BS + c4) * 4,
                 Bg + (size_t)row * ldb + c4, (bnoff + c4) < N);
        }
        asm volatile("cp.async.commit_group;");
    }

    for (int kt = 0; kt < KT; kt++) {
        int st = kt & 1;
        if (kt + 1 < KT) {
            int ns = st ^ 1;
            int k0 = (kt + 1) * BK;
#pragma unroll
            for (int i = 0; i < ALD; i++) {
                int f = tid + 256 * i;
                int row = f >> 3, c4 = (f & 7) * 4;
                cp16(as_base + (unsigned)(ns * BM * AS + row * AS + c4) * 4,
                     Ag + (size_t)row * lda + k0 + c4, true);
            }
#pragma unroll
            for (int i = 0; i < BLD; i++) {
                int f = tid + 256 * i;
                int row = f / (BN / 4), c4 = (f % (BN / 4)) * 4;
                cp16(bs_base + (unsigned)(ns * BK * BS + row * BS + c4) * 4,
                     Bg + (size_t)(k0 + row) * ldb + c4, (bnoff + c4) < N);
            }
            asm volatile("cp.async.commit_group;");
            asm volatile("cp.async.wait_group %0;" :: "n"(1));
        } else {
            asm volatile("cp.async.wait_group %0;" :: "n"(0));
        }
        __syncthreads();

        float* Asr = As_ + st * BM * AS;
        const float* Bsr = Bs_ + st * BK * BS;

        if (PEXP) {
            // scores -> probs; also emit unrounded probs to attn_out [b,q,k,h]
            float* base = Asr + xrow * AS + xc0;
            float* op = aout_base + (size_t)kt * 32 * 16;
#pragma unroll
            for (int i = 0; i < 16; i++) {
                float p = __expf(base[i]) * sinv;
                op[i * 16] = p;
                base[i] = frnd(p);
            }
            __syncthreads();
        }

#pragma unroll
        for (int kk = 0; kk < BK; kk += 8) {
            unsigned a[MT][4], b[NT][2];
            int ar = lane >> 2, ac = kk + (lane & 3);
#pragma unroll
            for (int m_ = 0; m_ < MT; m_++) {
                int r = wm + m_ * 16 + ar;
                a[m_][0] = __float_as_uint(Asr[r * AS + ac]);
                a[m_][1] = __float_as_uint(Asr[(r + 8) * AS + ac]);
                a[m_][2] = __float_as_uint(Asr[r * AS + ac + 4]);
                a[m_][3] = __float_as_uint(Asr[(r + 8) * AS + ac + 4]);
            }
            int br = kk + (lane & 3), bc = wn + (lane >> 2);
#pragma unroll
            for (int n_ = 0; n_ < NT; n_++) {
                b[n_][0] = __float_as_uint(Bsr[br * BS + bc + n_ * 8]);
                b[n_][1] = __float_as_uint(Bsr[(br + 4) * BS + bc + n_ * 8]);
            }
#pragma unroll
            for (int m_ = 0; m_ < MT; m_++)
#pragma unroll
                for (int n_ = 0; n_ < NT; n_++)
                    mma_tf32(acc[m_][n_], a[m_], b[n_]);
        }
        __syncthreads();
    }

    // epilogue (+ deterministic exp-sum reduction for SCOREBIAS)
    float esum[MT][2];
    if (EPI == EPI_SCOREBIAS) {
#pragma unroll
        for (int m_ = 0; m_ < MT; m_++) { esum[m_][0] = 0.f; esum[m_][1] = 0.f; }
    }
#pragma unroll
    for (int m_ = 0; m_ < MT; m_++) {
#pragma unroll
        for (int n_ = 0; n_ < NT; n_++) {
#pragma unroll
            for (int e = 0; e < 4; e++) {
                int m = bm * BM + wm + m_ * 16 + (lane >> 2) + (e >> 1) * 8;
                int n = bnoff + wn + n_ * 8 + (lane & 3) * 2 + (e & 1);
                if (n >= N) continue;
                float v = acc[m_][n_][e];
                size_t idx = coff + (size_t)m * ldc + n;
                if (EPI == EPI_PROJ4) {
                    if (bsel == 0) {
                        C[idx] = frnd(v * 0.125f);
                    } else if (bsel == 1) {
                        size_t o = (size_t)(m >> 10) * (1u << 20) + (size_t)n * 1024 + (m & 1023);
                        xa.Ckt[o] = frnd(v);
                    } else if (bsel == 2) {
                        xa.Cv[idx] = frnd(v);
                    } else {
                        float zz = v + xa.bg[n];
                        xa.Cg[idx] = 1.f / (1.f + __expf(-zz));
                    }
                } else if (EPI == EPI_SCOREBIAS) {
                    float t = v + xa.eb[((size_t)(z1 * 1024 + m) * 1024 + n) * 16 + z2];
                    if (mask[z1 * 1024 + n]) t = -CUDART_INF_F;
                    C[idx] = t;
                    esum[m_][e >> 1] += __expf(t);
                } else if (EPI == EPI_GATE) {
                    C[idx] = frnd(v * res[idx]);
                } else if (EPI == EPI_RESBIAS) {
                    C[idx] = v + bias[n] + res[idx];
                } else if (EPI == EPI_SILU) {
                    float zz = v + bias[n];
                    C[idx] = frnd(zz / (1.f + __expf(-zz)));
                }
            }
        }
    }

    if (EPI == EPI_SCOREBIAS) {
        float* rowsum = As_;              // smem reuse (free after last sync)
        if (tid < 128) rowsum[tid] = 0.f;
        __syncthreads();
#pragma unroll
        for (int m_ = 0; m_ < MT; m_++) {
#pragma unroll
            for (int rh = 0; rh < 2; rh++) {
                float val = esum[m_][rh];
                val += __shfl_xor_sync(0xffffffffu, val, 1);
                val += __shfl_xor_sync(0xffffffffu, val, 2);
                if ((lane & 3) == 0)      // 2 warps contribute per row: deterministic
                    atomicAdd(&rowsum[wm + m_ * 16 + (lane >> 2) + rh * 8], val);
            }
        }
        __syncthreads();
        if (tid < 128)
            xa.ps[((size_t)z * 1024 + bm * BM + tid) * 8 + bn] = rowsum[tid];
    }
}

// ---- RN-round copy (x) ------------------------------------------------------
__global__ __launch_bounds__(256)
void round_copy(const float* __restrict__ in, float* __restrict__ out)
{
    int i = blockIdx.x * 256 + threadIdx.x;
    float4 v = reinterpret_cast<const float4*>(in)[i];
    v.x = frnd(v.x); v.y = frnd(v.y); v.z = frnd(v.z); v.w = frnd(v.w);
    reinterpret_cast<float4*>(out)[i] = v;
}

// ---------------- row LayerNorm over D=1024 --------------------------------
template<bool RND>
__global__ __launch_bounds__(256)
void ln_kernel(const float* __restrict__ in, float* __restrict__ out,
               const float* __restrict__ gg, const float* __restrict__ bb)
{
    int row = blockIdx.x;
    int tid = threadIdx.x;
    float4 v = reinterpret_cast<const float4*>(in + (size_t)row * 1024)[tid];
    float s  = v.x + v.y + v.z + v.w;
    float ss = v.x * v.x + v.y * v.y + v.z * v.z + v.w * v.w;
#pragma unroll
    for (int o = 16; o; o >>= 1) {
        s  += __shfl_xor_sync(0xffffffffu, s, o);
        ss += __shfl_xor_sync(0xffffffffu, ss, o);
    }
    __shared__ float rs[8], rss[8];
    if ((tid & 31) == 0) { rs[tid >> 5] = s; rss[tid >> 5] = ss; }
    __syncthreads();
    if (tid < 32) {
        float a = (tid < 8) ? rs[tid] : 0.f;
        float c = (tid < 8) ? rss[tid] : 0.f;
#pragma unroll
        for (int o = 4; o; o >>= 1) {
            a += __shfl_xor_sync(0xffffffffu, a, o);
            c += __shfl_xor_sync(0xffffffffu, c, o);
        }
        if (tid == 0) { rs[0] = a; rss[0] = c; }
    }
    __syncthreads();
    float mean = rs[0] * (1.f / 1024.f);
    float var  = rss[0] * (1.f / 1024.f) - mean * mean;
    float inv  = rsqrtf(var + 1e-5f);
    float4 g4 = ((const float4*)gg)[tid];
    float4 b4 = ((const float4*)bb)[tid];
    float4 o4;
    o4.x = (v.x - mean) * inv * g4.x + b4.x;
    o4.y = (v.y - mean) * inv * g4.y + b4.y;
    o4.z = (v.z - mean) * inv * g4.z + b4.z;
    o4.w = (v.w - mean) * inv * g4.w + b4.w;
    if (RND) { o4.x = frnd(o4.x); o4.y = frnd(o4.y); o4.z = frnd(o4.z); o4.w = frnd(o4.w); }
    reinterpret_cast<float4*>(out + (size_t)row * 1024)[tid] = o4;
}

// ---------------- launcher --------------------------------------------------
extern "C" void kernel_launch(void* const* d_in, const int* in_sizes, int n_in,
                              void* d_out, int out_size)
{
    const float* x    = (const float*)d_in[0];
    const float* eb   = (const float*)d_in[1];
    const unsigned char* mask = (const unsigned char*)d_in[2];
    const float* wq   = (const float*)d_in[3];
    const float* wk   = (const float*)d_in[4];
    const float* wv   = (const float*)d_in[5];
    const float* wo   = (const float*)d_in[6];
    const float* bo   = (const float*)d_in[7];
    const float* wg   = (const float*)d_in[8];
    const float* bg   = (const float*)d_in[9];
    const float* w1   = (const float*)d_in[10];
    const float* b1   = (const float*)d_in[11];
    const float* w2   = (const float*)d_in[12];
    const float* b2   = (const float*)d_in[13];
    const float* ln1g = (const float*)d_in[14];
    const float* ln1b = (const float*)d_in[15];
    const float* ln2g = (const float*)d_in[16];
    const float* ln2b = (const float*)d_in[17];

    float* out_x    = (float*)d_out;
    float* out_attn = (float*)d_out + (size_t)NTOK * 1024;

    float *xr, *q, *kt, *v, *g, *s, *ps, *o, *r1, *y, *u, *r2;
    cudaGetSymbolAddress((void**)&xr,  g_xr);
    cudaGetSymbolAddress((void**)&q,   g_q);
    cudaGetSymbolAddress((void**)&kt,  g_kt);
    cudaGetSymbolAddress((void**)&v,   g_v);
    cudaGetSymbolAddress((void**)&g,   g_gate);
    cudaGetSymbolAddress((void**)&s,   g_s);
    cudaGetSymbolAddress((void**)&ps,  g_ps);
    cudaGetSymbolAddress((void**)&o,   g_o);
    cudaGetSymbolAddress((void**)&r1,  g_r1);
    cudaGetSymbolAddress((void**)&y,   g_y);
    cudaGetSymbolAddress((void**)&u,   g_u);
    cudaGetSymbolAddress((void**)&r2,  g_r2);

    const int SM128 = (2 * (128 * 36 + 32 * 136)) * 4;  // 71680
    const int SM64  = (2 * (128 * 36 + 32 * 72)) * 4;   // 55296
    cudaFuncSetAttribute(tgemm<128, EPI_PROJ4, false, false>,
                         cudaFuncAttributeMaxDynamicSharedMemorySize, SM128);
    cudaFuncSetAttribute(tgemm<128, EPI_SCOREBIAS, true, false>,
                         cudaFuncAttributeMaxDynamicSharedMemorySize, SM128);
    cudaFuncSetAttribute(tgemm<64, EPI_GATE, true, true>,
                         cudaFuncAttributeMaxDynamicSharedMemorySize, SM64);
    cudaFuncSetAttribute(tgemm<128, EPI_RESBIAS, false, false>,
                         cudaFuncAttributeMaxDynamicSharedMemorySize, SM128);
    cudaFuncSetAttribute(tgemm<128, EPI_SILU, false, false>,
                         cudaFuncAttributeMaxDynamicSharedMemorySize, SM128);

    XArgs xa{};
    xa.bg = bg; xa.eb = eb; xa.ps = ps; xa.aout = out_attn;

    // 0) RN-round x
    round_copy<<<2048, 256>>>(x, xr);

    // 1) fused projections
    {
        XArgs pa = xa;
        pa.Bw1 = wk; pa.Bw2 = wv; pa.Bw3 = wg;
        pa.Ckt = kt; pa.Cv = v;  pa.Cg = g;
        tgemm<128, EPI_PROJ4, false, false><<<dim3(32, 16, 1), 256, SM128>>>(
            xr, wq, q, NTOK, 1024, 1024, 1024, 1024, 1024,
            1, 0, 0, 0, 0, 0, 0, nullptr, nullptr, nullptr, pa);
    }

    // 2) scores = Q_h @ Kt_h + edge_bias; epilogue emits exp-sum partials
    tgemm<128, EPI_SCOREBIAS, true, false><<<dim3(32, 8, 8), 256, SM128>>>(
        q, kt, s, 1024, 1024, 64, 1024, 1024, 1024,
        16,
        (long long)1048576, 64,
        (long long)1048576, 65536,
        (long long)16777216, 1048576,
        nullptr, nullptr, mask, xa);

    // 3) o = (softmax(scores) @ V_h) * gate — transform also writes attn_out
    tgemm<64, EPI_GATE, true, true><<<dim3(32, 1, 8), 256, SM64>>>(
        s, v, o, 1024, 64, 1024, 1024, 1024, 1024,
        16,
        (long long)16777216, 1048576,
        (long long)1048576, 64,
        (long long)1048576, 64,
        nullptr, g, nullptr, xa);

    // 4) r1 = o @ wo + bo + x ; LN1 -> y
    tgemm<128, EPI_RESBIAS, false, false><<<dim3(8, 16, 1), 256, SM128>>>(
        o, wo, r1, NTOK, 1024, 1024, 1024, 1024, 1024,
        1, 0, 0, 0, 0, 0, 0, bo, x, nullptr, xa);
    ln_kernel<true><<<NTOK, 256>>>(r1, y, ln1g, ln1b);

    // 5) FFN
    tgemm<128, EPI_SILU, false, false><<<dim3(16, 16, 1), 256, SM128>>>(
        y, w1, u, NTOK, FFN, 1024, 1024, FFN, FFN,
        1, 0, 0, 0, 0, 0, 0, b1, nullptr, nullptr, xa);
    tgemm<128, EPI_RESBIAS, false, false><<<dim3(8, 16, 1), 256, SM128>>>(
        u, w2, r2, NTOK, 1024, FFN, FFN, 1024, 1024,
        1, 0, 0, 0, 0, 0, 0, b2, y, nullptr, xa);
    ln_kernel<false><<<NTOK, 256>>>(r2, out_x, ln2g, ln2b);
}

// round 14
// speedup vs baseline: 1.1523x; 1.1523x over previous
#include <cuda_runtime.h>
#include <math_constants.h>

#define NTOK  2048
#define FFN   2048

// ---------------- scratch ----------------
__device__ float g_xr  [NTOK * 1024];
__device__ float g_q   [NTOK * 1024];
__device__ float g_kt  [2 * 1024 * 1024];
__device__ float g_v   [NTOK * 1024];
__device__ float g_gate[NTOK * 1024];
__device__ float g_s   [(size_t)2 * 16 * 1024 * 1024];
__device__ float g_ps  [32 * 1024 * 8];          // per-(b,h,q) exp-sum partials
__device__ float g_o   [NTOK * 1024];
__device__ float g_r1  [NTOK * 1024];
__device__ float g_y   [NTOK * 1024];
__device__ float g_u   [NTOK * FFN];
__device__ float g_r2  [NTOK * 1024];

enum { EPI_PROJ4 = 0, EPI_SCOREBIAS = 1, EPI_GATE = 2, EPI_RESBIAS = 3, EPI_SILU = 4 };

struct XArgs {
    const float* Bw1; const float* Bw2; const float* Bw3;  // wk, wv, wg
    float* Ckt; float* Cv; float* Cg;                      // kt, v, gate outputs
    const float* bg;                                       // gate bias
    const float* eb;                                       // edge bias [b,q,k,h]
    float* ps;                                             // exp-sum partials
};

__device__ __forceinline__ unsigned f2tf32(float f) {
    unsigned r;
    asm("cvt.rna.tf32.f32 %0, %1;" : "=r"(r) : "f"(f));
    return r;
}
__device__ __forceinline__ float frnd(float f) { return __uint_as_float(f2tf32(f)); }

__device__ __forceinline__ void gdc_wait()   { asm volatile("griddepcontrol.wait;" ::: "memory"); }
__device__ __forceinline__ void gdc_launch() { asm volatile("griddepcontrol.launch_dependents;"); }

__device__ __forceinline__ void cp16(unsigned dst, const void* src, bool pred) {
    int sz = pred ? 16 : 0;
    asm volatile("cp.async.cg.shared.global [%0], [%1], 16, %2;"
                 :: "r"(dst), "l"(src), "r"(sz));
}

__device__ __forceinline__ void mma_tf32(float* c, const unsigned* a, const unsigned* b) {
    asm volatile(
        "mma.sync.aligned.m16n8k8.row.col.f32.tf32.tf32.f32 "
        "{%0,%1,%2,%3}, {%4,%5,%6,%7}, {%8,%9}, {%0,%1,%2,%3};"
        : "+f"(c[0]), "+f"(c[1]), "+f"(c[2]), "+f"(c[3])
        : "r"(a[0]), "r"(a[1]), "r"(a[2]), "r"(a[3]), "r"(b[0]), "r"(b[1]));
}

// ====== R6-proven 2-stage cp.async TF32 GEMM, BK=32, PDL-aware =============
// BIND: B operand is a kernel input (weights) — safe to prefetch before gdc_wait
template<int BN, int EPI, bool ZX, bool PEXP, bool BIND>
__global__ __launch_bounds__(256, 2)
void tgemm(const float* __restrict__ A, const float* __restrict__ B,
           float* __restrict__ C, int M, int N, int K,
           int lda, int ldb, int ldc, int zdiv,
           long long sA1, long long sA2, long long sB1, long long sB2,
           long long sC1, long long sC2,
           const float* __restrict__ bias, const float* __restrict__ res,
           const unsigned char* __restrict__ mask, XArgs xa)
{
    constexpr int BM = 128, BK = 32, AS = BK + 4, BS = BN + 8;
    constexpr int MT = 2;
    constexpr int NT = BN / 16;
    constexpr int WN = BN / 2;

    extern __shared__ float smem[];
    float* As_ = smem;
    float* Bs_ = smem + 2 * BM * AS;

    int z, bn, bm;
    if (ZX) { z = blockIdx.x; bn = blockIdx.y; bm = blockIdx.z; }
    else    { z = blockIdx.z; bn = blockIdx.x; bm = blockIdx.y; }
    int z1 = z / zdiv, z2 = z - z1 * zdiv;
    A += (size_t)z1 * sA1 + (size_t)z2 * sA2;
    size_t coff = (size_t)z1 * sC1 + (size_t)z2 * sC2;

    const float* Bbase = B;
    int bnoff = bn * BN;
    int bsel = 0;
    if (EPI == EPI_PROJ4) {
        bsel = bn >> 3;
        bnoff = (bn & 7) * 128;
        Bbase = (bsel == 0) ? B : (bsel == 1) ? xa.Bw1 : (bsel == 2) ? xa.Bw2 : xa.Bw3;
    } else {
        Bbase += (size_t)z1 * sB1 + (size_t)z2 * sB2;
    }

    int tid = threadIdx.x, lane = tid & 31, wid = tid >> 5;
    int wm = (wid & 3) * 32;
    int wn = (wid >> 2) * WN;

    unsigned as_base = (unsigned)__cvta_generic_to_shared(As_);
    unsigned bs_base = (unsigned)__cvta_generic_to_shared(Bs_);

    const float* Ag = A + (size_t)(bm * BM) * lda;
    const float* Bg = Bbase + bnoff;

    constexpr int ALD = (BM * BK) / (256 * 4);
    constexpr int BLD = (BK * BN) / (256 * 4);

    // independent weight prefetch overlaps predecessor tail
    if (BIND) {
#pragma unroll
        for (int i = 0; i < BLD; i++) {
            int f = tid + 256 * i;
            int row = f / (BN / 4), c4 = (f % (BN / 4)) * 4;
            cp16(bs_base + (unsigned)(row * BS + c4) * 4,
                 Bg + (size_t)row * ldb + c4, (bnoff + c4) < N);
        }
    }

    gdc_wait();      // predecessor outputs now visible
    gdc_launch();    // let successor begin its independent prologue

    float sinv = 0.f;
    int xrow = tid >> 1, xc0 = (tid & 1) * 16;
    if (PEXP) {
        int qg = bm * BM + xrow;
        const float* p8 = xa.ps + ((size_t)z * 1024 + qg) * 8;
        float sum = ((p8[0] + p8[1]) + (p8[2] + p8[3]))
                  + ((p8[4] + p8[5]) + (p8[6] + p8[7]));
        sinv = 1.f / sum;
    }

    float acc[MT][NT][4] = {};
    int KT = K / BK;

    {
#pragma unroll
        for (int i = 0; i < ALD; i++) {
            int f = tid + 256 * i;
            int row = f >> 3, c4 = (f & 7) * 4;
            cp16(as_base + (unsigned)(row * AS + c4) * 4,
                 Ag + (size_t)row * lda + c4, true);
        }
        if (!BIND) {
#pragma unroll
            for (int i = 0; i < BLD; i++) {
                int f = tid + 256 * i;
                int row = f / (BN / 4), c4 = (f % (BN / 4)) * 4;
                cp16(bs_base + (unsigned)(row * BS + c4) * 4,
                     Bg + (size_t)row * ldb + c4, (bnoff + c4) < N);
            }
        }
        asm volatile("cp.async.commit_group;");
    }

    for (int kt = 0; kt < KT; kt++) {
        int st = kt & 1;
        if (kt + 1 < KT) {
            int ns = st ^ 1;
            int k0 = (kt + 1) * BK;
#pragma unroll
            for (int i = 0; i < ALD; i++) {
                int f = tid + 256 * i;
                int row = f >> 3, c4 = (f & 7) * 4;
                cp16(as_base + (unsigned)(ns * BM * AS + row * AS + c4) * 4,
                     Ag + (size_t)row * lda + k0 + c4, true);
            }
#pragma unroll
            for (int i = 0; i < BLD; i++) {
                int f = tid + 256 * i;
                int row = f / (BN / 4), c4 = (f % (BN / 4)) * 4;
                cp16(bs_base + (unsigned)(ns * BK * BS + row * BS + c4) * 4,
                     Bg + (size_t)(k0 + row) * ldb + c4, (bnoff + c4) < N);
            }
            asm volatile("cp.async.commit_group;");
            asm volatile("cp.async.wait_group %0;" :: "n"(1));
        } else {
            asm volatile("cp.async.wait_group %0;" :: "n"(0));
        }
        __syncthreads();

        float* Asr = As_ + st * BM * AS;
        const float* Bsr = Bs_ + st * BK * BS;

        if (PEXP) {
            float* base = Asr + xrow * AS + xc0;
#pragma unroll
            for (int i = 0; i < 16; i++) {
                float p = __expf(base[i]) * sinv;
                base[i] = frnd(p);
            }
            __syncthreads();
        }

#pragma unroll
        for (int kk = 0; kk < BK; kk += 8) {
            unsigned a[MT][4], b[NT][2];
            int ar = lane >> 2, ac = kk + (lane & 3);
#pragma unroll
            for (int m_ = 0; m_ < MT; m_++) {
                int r = wm + m_ * 16 + ar;
                a[m_][0] = __float_as_uint(Asr[r * AS + ac]);
                a[m_][1] = __float_as_uint(Asr[(r + 8) * AS + ac]);
                a[m_][2] = __float_as_uint(Asr[r * AS + ac + 4]);
                a[m_][3] = __float_as_uint(Asr[(r + 8) * AS + ac + 4]);
            }
            int br = kk + (lane & 3), bc = wn + (lane >> 2);
#pragma unroll
            for (int n_ = 0; n_ < NT; n_++) {
                b[n_][0] = __float_as_uint(Bsr[br * BS + bc + n_ * 8]);
                b[n_][1] = __float_as_uint(Bsr[(br + 4) * BS + bc + n_ * 8]);
            }
#pragma unroll
            for (int m_ = 0; m_ < MT; m_++)
#pragma unroll
                for (int n_ = 0; n_ < NT; n_++)
                    mma_tf32(acc[m_][n_], a[m_], b[n_]);
        }
        __syncthreads();
    }

    // epilogue (+ deterministic exp-sum reduction for SCOREBIAS)
    float esum[MT][2];
    if (EPI == EPI_SCOREBIAS) {
#pragma unroll
        for (int m_ = 0; m_ < MT; m_++) { esum[m_][0] = 0.f; esum[m_][1] = 0.f; }
    }
#pragma unroll
    for (int m_ = 0; m_ < MT; m_++) {
#pragma unroll
        for (int n_ = 0; n_ < NT; n_++) {
#pragma unroll
            for (int e = 0; e < 4; e++) {
                int m = bm * BM + wm + m_ * 16 + (lane >> 2) + (e >> 1) * 8;
                int n = bnoff + wn + n_ * 8 + (lane & 3) * 2 + (e & 1);
                if (n >= N) continue;
                float v = acc[m_][n_][e];
                size_t idx = coff + (size_t)m * ldc + n;
                if (EPI == EPI_PROJ4) {
                    if (bsel == 0) {
                        C[idx] = frnd(v * 0.125f);
                    } else if (bsel == 1) {
                        size_t o = (size_t)(m >> 10) * (1u << 20) + (size_t)n * 1024 + (m & 1023);
                        xa.Ckt[o] = frnd(v);
                    } else if (bsel == 2) {
                        xa.Cv[idx] = frnd(v);
                    } else {
                        float zz = v + xa.bg[n];
                        xa.Cg[idx] = 1.f / (1.f + __expf(-zz));
                    }
                } else if (EPI == EPI_SCOREBIAS) {
                    float t = v + xa.eb[((size_t)(z1 * 1024 + m) * 1024 + n) * 16 + z2];
                    if (mask[z1 * 1024 + n]) t = -CUDART_INF_F;
                    C[idx] = t;
                    esum[m_][e >> 1] += __expf(t);
                } else if (EPI == EPI_GATE) {
                    C[idx] = frnd(v * res[idx]);
                } else if (EPI == EPI_RESBIAS) {
                    C[idx] = v + bias[n] + res[idx];
                } else if (EPI == EPI_SILU) {
                    float zz = v + bias[n];
                    C[idx] = frnd(zz / (1.f + __expf(-zz)));
                }
            }
        }
    }

    if (EPI == EPI_SCOREBIAS) {
        float* rowsum = As_;              // smem reuse (free after last sync)
        if (tid < 128) rowsum[tid] = 0.f;
        __syncthreads();
#pragma unroll
        for (int m_ = 0; m_ < MT; m_++) {
#pragma unroll
            for (int rh = 0; rh < 2; rh++) {
                float val = esum[m_][rh];
                val += __shfl_xor_sync(0xffffffffu, val, 1);
                val += __shfl_xor_sync(0xffffffffu, val, 2);
                if ((lane & 3) == 0)      // 2 warps contribute per row: deterministic
                    atomicAdd(&rowsum[wm + m_ * 16 + (lane >> 2) + rh * 8], val);
            }
        }
        __syncthreads();
        if (tid < 128)
            xa.ps[((size_t)z * 1024 + bm * BM + tid) * 8 + bn] = rowsum[tid];
    }
}

// ---- RN-round copy (x) — reads only true inputs: no wait -------------------
__global__ __launch_bounds__(256)
void round_copy(const float* __restrict__ in, float* __restrict__ out)
{
    gdc_launch();
    int i = blockIdx.x * 256 + threadIdx.x;
    float4 v = reinterpret_cast<const float4*>(in)[i];
    v.x = frnd(v.x); v.y = frnd(v.y); v.z = frnd(v.z); v.w = frnd(v.w);
    reinterpret_cast<float4*>(out)[i] = v;
}

// ------- attn_out writer [b,q,k,h] using precomputed exp-sums ---------------
__global__ __launch_bounds__(512)
void attn_writer(const float* __restrict__ s, const float* __restrict__ ps,
                 float* __restrict__ attn_out)
{
    gdc_wait();
    int q = blockIdx.x;
    int b = blockIdx.y;
    int w    = threadIdx.x >> 5;
    int lane = threadIdx.x & 31;
    const float* row = s + (((size_t)(b * 16 + w) * 1024 + q)) * 1024;

    const float* p8 = ps + ((size_t)(b * 16 + w) * 1024 + q) * 8;
    float sum = ((p8[0] + p8[1]) + (p8[2] + p8[3]))
              + ((p8[4] + p8[5]) + (p8[6] + p8[7]));
    float inv = 1.f / sum;

    float v[32];
#pragma unroll
    for (int i = 0; i < 32; i++)
        v[i] = __expf(row[i * 32 + lane]) * inv;

    __shared__ float tile[16 * 513];
    float* out = attn_out + ((size_t)(b * 1024 + q)) * 16384;
#pragma unroll
    for (int half = 0; half < 2; half++) {
        __syncthreads();
#pragma unroll
        for (int i = 0; i < 16; i++) {
            int k = (half * 16 + i) * 32 + lane;
            tile[w * 513 + (k - half * 512)] = v[half * 16 + i];
        }
        __syncthreads();
        for (int idx = threadIdx.x; idx < 8192; idx += 512) {
            int k = idx >> 4, h = idx & 15;
            out[half * 8192 + idx] = tile[h * 513 + k];
        }
    }
}

// ---------------- row LayerNorm over D=1024 --------------------------------
template<bool RND>
__global__ __launch_bounds__(256)
void ln_kernel(const float* __restrict__ in, float* __restrict__ out,
               const float* __restrict__ gg, const float* __restrict__ bb)
{
    gdc_wait();
    gdc_launch();
    int row = blockIdx.x;
    int tid = threadIdx.x;
    float4 v = reinterpret_cast<const float4*>(in + (size_t)row * 1024)[tid];
    float s  = v.x + v.y + v.z + v.w;
    float ss = v.x * v.x + v.y * v.y + v.z * v.z + v.w * v.w;
#pragma unroll
    for (int o = 16; o; o >>= 1) {
        s  += __shfl_xor_sync(0xffffffffu, s, o);
        ss += __shfl_xor_sync(0xffffffffu, ss, o);
    }
    __shared__ float rs[8], rss[8];
    if ((tid & 31) == 0) { rs[tid >> 5] = s; rss[tid >> 5] = ss; }
    __syncthreads();
    if (tid < 32) {
        float a = (tid < 8) ? rs[tid] : 0.f;
        float c = (tid < 8) ? rss[tid] : 0.f;
#pragma unroll
        for (int o = 4; o; o >>= 1) {
            a += __shfl_xor_sync(0xffffffffu, a, o);
            c += __shfl_xor_sync(0xffffffffu, c, o);
        }
        if (tid == 0) { rs[0] = a; rss[0] = c; }
    }
    __syncthreads();
    float mean = rs[0] * (1.f / 1024.f);
    float var  = rss[0] * (1.f / 1024.f) - mean * mean;
    float inv  = rsqrtf(var + 1e-5f);
    float4 g4 = ((const float4*)gg)[tid];
    float4 b4 = ((const float4*)bb)[tid];
    float4 o4;
    o4.x = (v.x - mean) * inv * g4.x + b4.x;
    o4.y = (v.y - mean) * inv * g4.y + b4.y;
    o4.z = (v.z - mean) * inv * g4.z + b4.z;
    o4.w = (v.w - mean) * inv * g4.w + b4.w;
    if (RND) { o4.x = frnd(o4.x); o4.y = frnd(o4.y); o4.z = frnd(o4.z); o4.w = frnd(o4.w); }
    reinterpret_cast<float4*>(out + (size_t)row * 1024)[tid] = o4;
}

// ---------------- PDL launch helper -----------------------------------------
template<typename K, typename... Args>
static inline void launch_pdl(K kern, dim3 grid, dim3 block, size_t smem, Args... args)
{
    cudaLaunchConfig_t cfg{};
    cfg.gridDim = grid;
    cfg.blockDim = block;
    cfg.dynamicSmemBytes = smem;
    cfg.stream = 0;
    cudaLaunchAttribute at[1];
    at[0].id = cudaLaunchAttributeProgrammaticStreamSerialization;
    at[0].val.programmaticStreamSerializationAllowed = 1;
    cfg.attrs = at;
    cfg.numAttrs = 1;
    cudaLaunchKernelEx(&cfg, kern, args...);
}

// ---------------- launcher --------------------------------------------------
extern "C" void kernel_launch(void* const* d_in, const int* in_sizes, int n_in,
                              void* d_out, int out_size)
{
    const float* x    = (const float*)d_in[0];
    const float* eb   = (const float*)d_in[1];
    const unsigned char* mask = (const unsigned char*)d_in[2];
    const float* wq   = (const float*)d_in[3];
    const float* wk   = (const float*)d_in[4];
    const float* wv   = (const float*)d_in[5];
    const float* wo   = (const float*)d_in[6];
    const float* bo   = (const float*)d_in[7];
    const float* wg   = (const float*)d_in[8];
    const float* bg   = (const float*)d_in[9];
    const float* w1   = (const float*)d_in[10];
    const float* b1   = (const float*)d_in[11];
    const float* w2   = (const float*)d_in[12];
    const float* b2   = (const float*)d_in[13];
    const float* ln1g = (const float*)d_in[14];
    const float* ln1b = (const float*)d_in[15];
    const float* ln2g = (const float*)d_in[16];
    const float* ln2b = (const float*)d_in[17];

    float* out_x    = (float*)d_out;
    float* out_attn = (float*)d_out + (size_t)NTOK * 1024;

    float *xr, *q, *kt, *v, *g, *s, *ps, *o, *r1, *y, *u, *r2;
    cudaGetSymbolAddress((void**)&xr,  g_xr);
    cudaGetSymbolAddress((void**)&q,   g_q);
    cudaGetSymbolAddress((void**)&kt,  g_kt);
    cudaGetSymbolAddress((void**)&v,   g_v);
    cudaGetSymbolAddress((void**)&g,   g_gate);
    cudaGetSymbolAddress((void**)&s,   g_s);
    cudaGetSymbolAddress((void**)&ps,  g_ps);
    cudaGetSymbolAddress((void**)&o,   g_o);
    cudaGetSymbolAddress((void**)&r1,  g_r1);
    cudaGetSymbolAddress((void**)&y,   g_y);
    cudaGetSymbolAddress((void**)&u,   g_u);
    cudaGetSymbolAddress((void**)&r2,  g_r2);

    const int SM128 = (2 * (128 * 36 + 32 * 136)) * 4;  // 71680
    const int SM64  = (2 * (128 * 36 + 32 * 72)) * 4;   // 55296
    cudaFuncSetAttribute(tgemm<128, EPI_PROJ4, false, false, true>,
                         cudaFuncAttributeMaxDynamicSharedMemorySize, SM128);
    cudaFuncSetAttribute(tgemm<128, EPI_SCOREBIAS, true, false, false>,
                         cudaFuncAttributeMaxDynamicSharedMemorySize, SM128);
    cudaFuncSetAttribute(tgemm<64, EPI_GATE, true, true, false>,
                         cudaFuncAttributeMaxDynamicSharedMemorySize, SM64);
    cudaFuncSetAttribute(tgemm<128, EPI_RESBIAS, false, false, true>,
                         cudaFuncAttributeMaxDynamicSharedMemorySize, SM128);
    cudaFuncSetAttribute(tgemm<128, EPI_SILU, false, false, true>,
                         cudaFuncAttributeMaxDynamicSharedMemorySize, SM128);

    XArgs xa{};
    xa.bg = bg; xa.eb = eb; xa.ps = ps;

    // 0) RN-round x
    launch_pdl(round_copy, dim3(2048), dim3(256), 0, x, xr);

    // 1) fused projections (weights prefetched pre-wait)
    {
        XArgs pa = xa;
        pa.Bw1 = wk; pa.Bw2 = wv; pa.Bw3 = wg;
        pa.Ckt = kt; pa.Cv = v;  pa.Cg = g;
        launch_pdl(tgemm<128, EPI_PROJ4, false, false, true>,
                   dim3(32, 16, 1), dim3(256), SM128,
                   (const float*)xr, wq, q, NTOK, 1024, 1024, 1024, 1024, 1024,
                   1, 0LL, 0LL, 0LL, 0LL, 0LL, 0LL,
                   (const float*)nullptr, (const float*)nullptr,
                   (const unsigned char*)nullptr, pa);
    }

    // 2) scores = Q_h @ Kt_h + edge_bias; epilogue emits exp-sum partials
    launch_pdl(tgemm<128, EPI_SCOREBIAS, true, false, false>,
               dim3(32, 8, 8), dim3(256), SM128,
               (const float*)q, (const float*)kt, s, 1024, 1024, 64,
               1024, 1024, 1024, 16,
               (long long)1048576, (long long)64,
               (long long)1048576, (long long)65536,
               (long long)16777216, (long long)1048576,
               (const float*)nullptr, (const float*)nullptr, mask, xa);

    // 3) o = (softmax(scores) @ V_h) * gate
    launch_pdl(tgemm<64, EPI_GATE, true, true, false>,
               dim3(32, 1, 8), dim3(256), SM64,
               (const float*)s, (const float*)v, o, 1024, 64, 1024,
               1024, 1024, 1024, 16,
               (long long)16777216, (long long)1048576,
               (long long)1048576, (long long)64,
               (long long)1048576, (long long)64,
               (const float*)nullptr, (const float*)g,
               (const unsigned char*)nullptr, xa);

    // 4) r1 = o @ wo + bo + x ; LN1 -> y
    launch_pdl(tgemm<128, EPI_RESBIAS, false, false, true>,
               dim3(8, 16, 1), dim3(256), SM128,
               (const float*)o, wo, r1, NTOK, 1024, 1024, 1024, 1024, 1024,
               1, 0LL, 0LL, 0LL, 0LL, 0LL, 0LL,
               bo, x, (const unsigned char*)nullptr, xa);
    launch_pdl(ln_kernel<true>, dim3(NTOK), dim3(256), 0,
               (const float*)r1, y, ln1g, ln1b);

    // 5) FFN
    launch_pdl(tgemm<128, EPI_SILU, false, false, true>,
               dim3(16, 16, 1), dim3(256), SM128,
               (const float*)y, w1, u, NTOK, FFN, 1024, 1024, FFN, FFN,
               1, 0LL, 0LL, 0LL, 0LL, 0LL, 0LL,
               b1, (const float*)nullptr, (const unsigned char*)nullptr, xa);
    launch_pdl(tgemm<128, EPI_RESBIAS, false, false, true>,
               dim3(8, 16, 1), dim3(256), SM128,
               (const float*)u, w2, r2, NTOK, 1024, FFN, FFN, 1024, 1024,
               1, 0LL, 0LL, 0LL, 0LL, 0LL, 0LL,
               b2, y, (const unsigned char*)nullptr, xa);
    launch_pdl(ln_kernel<false>, dim3(NTOK), dim3(256), 0,
               (const float*)r2, out_x, ln2g, ln2b);

    // 6) attn_out writer (reads s + ps; all complete by chain induction)
    launch_pdl(attn_writer, dim3(1024, 2), dim3(512), 0,
               (const float*)s, (const float*)ps, out_attn);
}

// round 15
// speedup vs baseline: 1.2343x; 1.0712x over previous
#include <cuda_runtime.h>
#include <math_constants.h>

#define NTOK  2048
#define FFN   2048

// ---------------- scratch ----------------
__device__ float g_xr  [NTOK * 1024];
__device__ float g_q   [NTOK * 1024];
__device__ float g_kt  [2 * 1024 * 1024];
__device__ float g_v   [NTOK * 1024];
__device__ float g_gate[NTOK * 1024];
__device__ float g_s   [(size_t)2 * 16 * 1024 * 1024];   // exp(scores)
__device__ float g_ps  [32 * 1024 * 8];                  // exp-sum partials
__device__ float g_o   [NTOK * 1024];
__device__ float g_r1  [NTOK * 1024];
__device__ float g_y   [NTOK * 1024];
__device__ float g_u   [NTOK * FFN];
__device__ float g_r2  [NTOK * 1024];

enum { EPI_PROJ4 = 0, EPI_SCOREBIAS = 1, EPI_GATE = 2, EPI_RESBIAS = 3, EPI_SILU = 4 };

struct XArgs {
    const float* Bw1; const float* Bw2; const float* Bw3;  // wk, wv, wg
    float* Ckt; float* Cv; float* Cg;                      // kt, v, gate outputs
    const float* bg;                                       // gate bias
    const float* eb;                                       // edge bias [b,q,k,h]
    float* ps;                                             // exp-sum partials
};

__device__ __forceinline__ unsigned f2tf32(float f) {
    unsigned r;
    asm("cvt.rna.tf32.f32 %0, %1;" : "=r"(r) : "f"(f));
    return r;
}
__device__ __forceinline__ float frnd(float f) { return __uint_as_float(f2tf32(f)); }

__device__ __forceinline__ void cp16(unsigned dst, const void* src, bool pred) {
    int sz = pred ? 16 : 0;
    asm volatile("cp.async.cg.shared.global [%0], [%1], 16, %2;"
                 :: "r"(dst), "l"(src), "r"(sz));
}

__device__ __forceinline__ void mma_tf32(float* c, const unsigned* a, const unsigned* b) {
    asm volatile(
        "mma.sync.aligned.m16n8k8.row.col.f32.tf32.tf32.f32 "
        "{%0,%1,%2,%3}, {%4,%5,%6,%7}, {%8,%9}, {%0,%1,%2,%3};"
        : "+f"(c[0]), "+f"(c[1]), "+f"(c[2]), "+f"(c[3])
        : "r"(a[0]), "r"(a[1]), "r"(a[2]), "r"(a[3]), "r"(b[0]), "r"(b[1]));
}

// ====== R6-proven 2-stage cp.async TF32 GEMM, BK=32 ========================
template<int BN, int EPI, bool ZX, bool PEXP>
__global__ __launch_bounds__(256, 2)
void tgemm(const float* __restrict__ A, const float* __restrict__ B,
           float* __restrict__ C, int M, int N, int K,
           int lda, int ldb, int ldc, int zdiv,
           long long sA1, long long sA2, long long sB1, long long sB2,
           long long sC1, long long sC2,
           const float* __restrict__ bias, const float* __restrict__ res,
           const unsigned char* __restrict__ mask, XArgs xa)
{
    constexpr int BM = 128, BK = 32, AS = BK + 4, BS = BN + 8;
    constexpr int MT = 2;
    constexpr int NT = BN / 16;
    constexpr int WN = BN / 2;

    extern __shared__ float smem[];
    float* As_ = smem;
    float* Bs_ = smem + 2 * BM * AS;

    int z, bn, bm;
    if (ZX) { z = blockIdx.x; bn = blockIdx.y; bm = blockIdx.z; }
    else    { z = blockIdx.z; bn = blockIdx.x; bm = blockIdx.y; }
    int z1 = z / zdiv, z2 = z - z1 * zdiv;
    A += (size_t)z1 * sA1 + (size_t)z2 * sA2;
    size_t coff = (size_t)z1 * sC1 + (size_t)z2 * sC2;

    const float* Bbase = B;
    int bnoff = bn * BN;
    int bsel = 0;
    if (EPI == EPI_PROJ4) {
        bsel = bn >> 3;
        bnoff = (bn & 7) * 128;
        Bbase = (bsel == 0) ? B : (bsel == 1) ? xa.Bw1 : (bsel == 2) ? xa.Bw2 : xa.Bw3;
    } else {
        Bbase += (size_t)z1 * sB1 + (size_t)z2 * sB2;
    }

    int tid = threadIdx.x, lane = tid & 31, wid = tid >> 5;
    int wm = (wid & 3) * 32;
    int wn = (wid >> 2) * WN;

    float sinv = 0.f;
    int xrow = tid >> 1, xc0 = (tid & 1) * 16;
    if (PEXP) {
        int qg = bm * BM + xrow;
        const float* p8 = xa.ps + ((size_t)z * 1024 + qg) * 8;
        float sum = ((p8[0] + p8[1]) + (p8[2] + p8[3]))
                  + ((p8[4] + p8[5]) + (p8[6] + p8[7]));
        sinv = 1.f / sum;
    }

    unsigned as_base = (unsigned)__cvta_generic_to_shared(As_);
    unsigned bs_base = (unsigned)__cvta_generic_to_shared(Bs_);

    const float* Ag = A + (size_t)(bm * BM) * lda;
    const float* Bg = Bbase + bnoff;

    float acc[MT][NT][4] = {};

    constexpr int ALD = (BM * BK) / (256 * 4);
    constexpr int BLD = (BK * BN) / (256 * 4);

    int KT = K / BK;

    {
#pragma unroll
        for (int i = 0; i < ALD; i++) {
            int f = tid + 256 * i;
            int row = f >> 3, c4 = (f & 7) * 4;
            cp16(as_base + (unsigned)(row * AS + c4) * 4,
                 Ag + (size_t)row * lda + c4, true);
        }
#pragma unroll
        for (int i = 0; i < BLD; i++) {
            int f = tid + 256 * i;
            int row = f / (BN / 4), c4 = (f % (BN / 4)) * 4;
            cp16(bs_base + (unsigned)(row * BS + c4) * 4,
                 Bg + (size_t)row * ldb + c4, (bnoff + c4) < N);
        }
        asm volatile("cp.async.commit_group;");
    }

    for (int kt = 0; kt < KT; kt++) {
        int st = kt & 1;
        if (kt + 1 < KT) {
            int ns = st ^ 1;
            int k0 = (kt + 1) * BK;
#pragma unroll
            for (int i = 0; i < ALD; i++) {
                int f = tid + 256 * i;
                int row = f >> 3, c4 = (f & 7) * 4;
                cp16(as_base + (unsigned)(ns * BM * AS + row * AS + c4) * 4,
                     Ag + (size_t)row * lda + k0 + c4, true);
            }
#pragma unroll
            for (int i = 0; i < BLD; i++) {
                int f = tid + 256 * i;
                int row = f / (BN / 4), c4 = (f % (BN / 4)) * 4;
                cp16(bs_base + (unsigned)(ns * BK * BS + row * BS + c4) * 4,
                     Bg + (size_t)(k0 + row) * ldb + c4, (bnoff + c4) < N);
            }
            asm volatile("cp.async.commit_group;");
            asm volatile("cp.async.wait_group %0;" :: "n"(1));
        } else {
            asm volatile("cp.async.wait_group %0;" :: "n"(0));
        }
        __syncthreads();

        float* Asr = As_ + st * BM * AS;
        const float* Bsr = Bs_ + st * BK * BS;

        if (PEXP) {
            // s already holds exp(score); just normalize + RN-round
            float* base = Asr + xrow * AS + xc0;
#pragma unroll
            for (int i = 0; i < 16; i++)
                base[i] = frnd(base[i] * sinv);
            __syncthreads();
        }

#pragma unroll
        for (int kk = 0; kk < BK; kk += 8) {
            unsigned a[MT][4], b[NT][2];
            int ar = lane >> 2, ac = kk + (lane & 3);
#pragma unroll
            for (int m_ = 0; m_ < MT; m_++) {
                int r = wm + m_ * 16 + ar;
                a[m_][0] = __float_as_uint(Asr[r * AS + ac]);
                a[m_][1] = __float_as_uint(Asr[(r + 8) * AS + ac]);
                a[m_][2] = __float_as_uint(Asr[r * AS + ac + 4]);
                a[m_][3] = __float_as_uint(Asr[(r + 8) * AS + ac + 4]);
            }
            int br = kk + (lane & 3), bc = wn + (lane >> 2);
#pragma unroll
            for (int n_ = 0; n_ < NT; n_++) {
                b[n_][0] = __float_as_uint(Bsr[br * BS + bc + n_ * 8]);
                b[n_][1] = __float_as_uint(Bsr[(br + 4) * BS + bc + n_ * 8]);
            }
#pragma unroll
            for (int m_ = 0; m_ < MT; m_++)
#pragma unroll
                for (int n_ = 0; n_ < NT; n_++)
                    mma_tf32(acc[m_][n_], a[m_], b[n_]);
        }
        __syncthreads();
    }

    // epilogue (+ deterministic exp-sum reduction for SCOREBIAS)
    float esum[MT][2];
    if (EPI == EPI_SCOREBIAS) {
#pragma unroll
        for (int m_ = 0; m_ < MT; m_++) { esum[m_][0] = 0.f; esum[m_][1] = 0.f; }
    }
#pragma unroll
    for (int m_ = 0; m_ < MT; m_++) {
#pragma unroll
        for (int n_ = 0; n_ < NT; n_++) {
#pragma unroll
            for (int e = 0; e < 4; e++) {
                int m = bm * BM + wm + m_ * 16 + (lane >> 2) + (e >> 1) * 8;
                int n = bnoff + wn + n_ * 8 + (lane & 3) * 2 + (e & 1);
                if (n >= N) continue;
                float v = acc[m_][n_][e];
                size_t idx = coff + (size_t)m * ldc + n;
                if (EPI == EPI_PROJ4) {
                    if (bsel == 0) {
                        C[idx] = frnd(v * 0.125f);
                    } else if (bsel == 1) {
                        size_t o = (size_t)(m >> 10) * (1u << 20) + (size_t)n * 1024 + (m & 1023);
                        xa.Ckt[o] = frnd(v);
                    } else if (bsel == 2) {
                        xa.Cv[idx] = frnd(v);
                    } else {
                        float zz = v + xa.bg[n];
                        xa.Cg[idx] = 1.f / (1.f + __expf(-zz));
                    }
                } else if (EPI == EPI_SCOREBIAS) {
                    float t = v + xa.eb[((size_t)(z1 * 1024 + m) * 1024 + n) * 16 + z2];
                    if (mask[z1 * 1024 + n]) t = -CUDART_INF_F;
                    float ex = __expf(t);
                    C[idx] = ex;                     // store exp(score)
                    esum[m_][e >> 1] += ex;
                } else if (EPI == EPI_GATE) {
                    C[idx] = frnd(v * res[idx]);
                } else if (EPI == EPI_RESBIAS) {
                    C[idx] = v + bias[n] + res[idx];
                } else if (EPI == EPI_SILU) {
                    float zz = v + bias[n];
                    C[idx] = frnd(zz / (1.f + __expf(-zz)));
                }
            }
        }
    }

    if (EPI == EPI_SCOREBIAS) {
        float* rowsum = As_;              // smem reuse (free after last sync)
        if (tid < 128) rowsum[tid] = 0.f;
        __syncthreads();
#pragma unroll
        for (int m_ = 0; m_ < MT; m_++) {
#pragma unroll
            for (int rh = 0; rh < 2; rh++) {
                float val = esum[m_][rh];
                val += __shfl_xor_sync(0xffffffffu, val, 1);
                val += __shfl_xor_sync(0xffffffffu, val, 2);
                if ((lane & 3) == 0)      // 2 warps contribute per row: deterministic
                    atomicAdd(&rowsum[wm + m_ * 16 + (lane >> 2) + rh * 8], val);
            }
        }
        __syncthreads();
        if (tid < 128)
            xa.ps[((size_t)z * 1024 + bm * BM + tid) * 8 + bn] = rowsum[tid];
    }
}

// ---- RN-round copy (x) ------------------------------------------------------
__global__ __launch_bounds__(256)
void round_copy(const float* __restrict__ in, float* __restrict__ out)
{
    int i = blockIdx.x * 256 + threadIdx.x;
    float4 v = reinterpret_cast<const float4*>(in)[i];
    v.x = frnd(v.x); v.y = frnd(v.y); v.z = frnd(v.z); v.w = frnd(v.w);
    reinterpret_cast<float4*>(out)[i] = v;
}

// ------- attn_out writer: reads exp(s) + partials, no exp needed -------------
__global__ __launch_bounds__(512)
void attn_writer(const float* __restrict__ s, const float* __restrict__ ps,
                 float* __restrict__ attn_out)
{
    int q = blockIdx.x;
    int b = blockIdx.y;
    int w    = threadIdx.x >> 5;
    int lane = threadIdx.x & 31;
    const float* row = s + (((size_t)(b * 16 + w) * 1024 + q)) * 1024;

    const float* p8 = ps + ((size_t)(b * 16 + w) * 1024 + q) * 8;
    float sum = ((p8[0] + p8[1]) + (p8[2] + p8[3]))
              + ((p8[4] + p8[5]) + (p8[6] + p8[7]));
    float inv = 1.f / sum;

    float v[32];
#pragma unroll
    for (int i = 0; i < 32; i++)
        v[i] = row[i * 32 + lane] * inv;

    __shared__ float tile[16 * 513];
    float* out = attn_out + ((size_t)(b * 1024 + q)) * 16384;
#pragma unroll
    for (int half = 0; half < 2; half++) {
        __syncthreads();
#pragma unroll
        for (int i = 0; i < 16; i++) {
            int k = (half * 16 + i) * 32 + lane;
            tile[w * 513 + (k - half * 512)] = v[half * 16 + i];
        }
        __syncthreads();
        for (int idx = threadIdx.x; idx < 8192; idx += 512) {
            int k = idx >> 4, h = idx & 15;
            out[half * 8192 + idx] = tile[h * 513 + k];
        }
    }
}

// ---------------- row LayerNorm over D=1024 --------------------------------
template<bool RND>
__global__ __launch_bounds__(256)
void ln_kernel(const float* __restrict__ in, float* __restrict__ out,
               const float* __restrict__ gg, const float* __restrict__ bb)
{
    int row = blockIdx.x;
    int tid = threadIdx.x;
    float4 v = reinterpret_cast<const float4*>(in + (size_t)row * 1024)[tid];
    float s  = v.x + v.y + v.z + v.w;
    float ss = v.x * v.x + v.y * v.y + v.z * v.z + v.w * v.w;
#pragma unroll
    for (int o = 16; o; o >>= 1) {
        s  += __shfl_xor_sync(0xffffffffu, s, o);
        ss += __shfl_xor_sync(0xffffffffu, ss, o);
    }
    __shared__ float rs[8], rss[8];
    if ((tid & 31) == 0) { rs[tid >> 5] = s; rss[tid >> 5] = ss; }
    __syncthreads();
    if (tid < 32) {
        float a = (tid < 8) ? rs[tid] : 0.f;
        float c = (tid < 8) ? rss[tid] : 0.f;
#pragma unroll
        for (int o = 4; o; o >>= 1) {
            a += __shfl_xor_sync(0xffffffffu, a, o);
            c += __shfl_xor_sync(0xffffffffu, c, o);
        }
        if (tid == 0) { rs[0] = a; rss[0] = c; }
    }
    __syncthreads();
    float mean = rs[0] * (1.f / 1024.f);
    float var  = rss[0] * (1.f / 1024.f) - mean * mean;
    float inv  = rsqrtf(var + 1e-5f);
    float4 g4 = ((const float4*)gg)[tid];
    float4 b4 = ((const float4*)bb)[tid];
    float4 o4;
    o4.x = (v.x - mean) * inv * g4.x + b4.x;
    o4.y = (v.y - mean) * inv * g4.y + b4.y;
    o4.z = (v.z - mean) * inv * g4.z + b4.z;
    o4.w = (v.w - mean) * inv * g4.w + b4.w;
    if (RND) { o4.x = frnd(o4.x); o4.y = frnd(o4.y); o4.z = frnd(o4.z); o4.w = frnd(o4.w); }
    reinterpret_cast<float4*>(out + (size_t)row * 1024)[tid] = o4;
}

// ------- side stream + fork/join events (created once at module load) ------
struct StreamHolder {
    cudaStream_t s;
    cudaEvent_t  fork, join;
    StreamHolder() {
        cudaStreamCreateWithFlags(&s, cudaStreamNonBlocking);
        cudaEventCreateWithFlags(&fork, cudaEventDisableTiming);
        cudaEventCreateWithFlags(&join, cudaEventDisableTiming);
    }
};
static StreamHolder g_sh;

// ---------------- launcher --------------------------------------------------
extern "C" void kernel_launch(void* const* d_in, const int* in_sizes, int n_in,
                              void* d_out, int out_size)
{
    const float* x    = (const float*)d_in[0];
    const float* eb   = (const float*)d_in[1];
    const unsigned char* mask = (const unsigned char*)d_in[2];
    const float* wq   = (const float*)d_in[3];
    const float* wk   = (const float*)d_in[4];
    const float* wv   = (const float*)d_in[5];
    const float* wo   = (const float*)d_in[6];
    const float* bo   = (const float*)d_in[7];
    const float* wg   = (const float*)d_in[8];
    const float* bg   = (const float*)d_in[9];
    const float* w1   = (const float*)d_in[10];
    const float* b1   = (const float*)d_in[11];
    const float* w2   = (const float*)d_in[12];
    const float* b2   = (const float*)d_in[13];
    const float* ln1g = (const float*)d_in[14];
    const float* ln1b = (const float*)d_in[15];
    const float* ln2g = (const float*)d_in[16];
    const float* ln2b = (const float*)d_in[17];

    float* out_x    = (float*)d_out;
    float* out_attn = (float*)d_out + (size_t)NTOK * 1024;

    float *xr, *q, *kt, *v, *g, *s, *ps, *o, *r1, *y, *u, *r2;
    cudaGetSymbolAddress((void**)&xr,  g_xr);
    cudaGetSymbolAddress((void**)&q,   g_q);
    cudaGetSymbolAddress((void**)&kt,  g_kt);
    cudaGetSymbolAddress((void**)&v,   g_v);
    cudaGetSymbolAddress((void**)&g,   g_gate);
    cudaGetSymbolAddress((void**)&s,   g_s);
    cudaGetSymbolAddress((void**)&ps,  g_ps);
    cudaGetSymbolAddress((void**)&o,   g_o);
    cudaGetSymbolAddress((void**)&r1,  g_r1);
    cudaGetSymbolAddress((void**)&y,   g_y);
    cudaGetSymbolAddress((void**)&u,   g_u);
    cudaGetSymbolAddress((void**)&r2,  g_r2);

    const int SM128 = (2 * (128 * 36 + 32 * 136)) * 4;  // 71680
    const int SM64  = (2 * (128 * 36 + 32 * 72)) * 4;   // 55296
    cudaFuncSetAttribute(tgemm<128, EPI_PROJ4, false, false>,
                         cudaFuncAttributeMaxDynamicSharedMemorySize, SM128);
    cudaFuncSetAttribute(tgemm<128, EPI_SCOREBIAS, true, false>,
                         cudaFuncAttributeMaxDynamicSharedMemorySize, SM128);
    cudaFuncSetAttribute(tgemm<64, EPI_GATE, true, true>,
                         cudaFuncAttributeMaxDynamicSharedMemorySize, SM64);
    cudaFuncSetAttribute(tgemm<128, EPI_RESBIAS, false, false>,
                         cudaFuncAttributeMaxDynamicSharedMemorySize, SM128);
    cudaFuncSetAttribute(tgemm<128, EPI_SILU, false, false>,
                         cudaFuncAttributeMaxDynamicSharedMemorySize, SM128);

    XArgs xa{};
    xa.bg = bg; xa.eb = eb; xa.ps = ps;

    // 0) RN-round x
    round_copy<<<2048, 256>>>(x, xr);

    // 1) fused projections
    {
        XArgs pa = xa;
        pa.Bw1 = wk; pa.Bw2 = wv; pa.Bw3 = wg;
        pa.Ckt = kt; pa.Cv = v;  pa.Cg = g;
        tgemm<128, EPI_PROJ4, false, false><<<dim3(32, 16, 1), 256, SM128>>>(
            xr, wq, q, NTOK, 1024, 1024, 1024, 1024, 1024,
            1, 0, 0, 0, 0, 0, 0, nullptr, nullptr, nullptr, xa = pa);
    }

    // 2) scores -> exp(scores) in s; epilogue emits exp-sum partials
    {
        XArgs sa{};
        sa.bg = bg; sa.eb = eb; sa.ps = ps;
        tgemm<128, EPI_SCOREBIAS, true, false><<<dim3(32, 8, 8), 256, SM128>>>(
            q, kt, s, 1024, 1024, 64, 1024, 1024, 1024,
            16,
            (long long)1048576, 64,
            (long long)1048576, 65536,
            (long long)16777216, 1048576,
            nullptr, nullptr, mask, sa);

        // 3) o = (probs @ V_h) * gate  — transform: mul by sinv only
        tgemm<64, EPI_GATE, true, true><<<dim3(32, 1, 8), 256, SM64>>>(
            s, v, o, 1024, 64, 1024, 1024, 1024, 1024,
            16,
            (long long)16777216, 1048576,
            (long long)1048576, 64,
            (long long)1048576, 64,
            nullptr, g, nullptr, sa);

        // fork: attn_out writer overlaps the wo/FFN window (DRAM headroom)
        cudaEventRecord(g_sh.fork, 0);
        cudaStreamWaitEvent(g_sh.s, g_sh.fork, 0);
        attn_writer<<<dim3(1024, 2), 512, 0, g_sh.s>>>(s, ps, out_attn);
        cudaEventRecord(g_sh.join, g_sh.s);

        // 4) r1 = o @ wo + bo + x ; LN1 -> y
        tgemm<128, EPI_RESBIAS, false, false><<<dim3(8, 16, 1), 256, SM128>>>(
            o, wo, r1, NTOK, 1024, 1024, 1024, 1024, 1024,
            1, 0, 0, 0, 0, 0, 0, bo, x, nullptr, sa);
        ln_kernel<true><<<NTOK, 256>>>(r1, y, ln1g, ln1b);

        // 5) FFN
        tgemm<128, EPI_SILU, false, false><<<dim3(16, 16, 1), 256, SM128>>>(
            y, w1, u, NTOK, FFN, 1024, 1024, FFN, FFN,
            1, 0, 0, 0, 0, 0, 0, b1, nullptr, nullptr, sa);
        tgemm<128, EPI_RESBIAS, false, false><<<dim3(8, 16, 1), 256, SM128>>>(
            u, w2, r2, NTOK, 1024, FFN, FFN, 1024, 1024,
            1, 0, 0, 0, 0, 0, 0, b2, y, nullptr, sa);
        ln_kernel<false><<<NTOK, 256>>>(r2, out_x, ln2g, ln2b);
    }

    // join: ensure the attn_out writer finished before the graph ends
    cudaStreamWaitEvent(0, g_sh.join, 0);
}

// round 16
// speedup vs baseline: 1.2712x; 1.0299x over previous
#include <cuda_runtime.h>
#include <math_constants.h>

#define NTOK  2048
#define FFN   2048

// ---------------- scratch ----------------
__device__ float g_xr  [NTOK * 1024];
__device__ float g_q   [NTOK * 1024];
__device__ float g_kt  [2 * 1024 * 1024];
__device__ float g_v   [NTOK * 1024];
__device__ float g_gate[NTOK * 1024];
__device__ float g_s   [(size_t)2 * 16 * 1024 * 1024];   // exp(scores)
__device__ float g_ps  [32 * 1024 * 8];                  // exp-sum partials
__device__ float g_o   [NTOK * 1024];
__device__ float g_r1  [NTOK * 1024];
__device__ float g_y   [NTOK * 1024];
__device__ float g_u   [NTOK * FFN];
__device__ float g_r2  [NTOK * 1024];

enum { EPI_PROJ4 = 0, EPI_SCOREBIAS = 1, EPI_GATE = 2, EPI_RESBIAS = 3, EPI_SILU = 4 };

struct XArgs {
    const float* Bw1; const float* Bw2; const float* Bw3;  // wk, wv, wg
    float* Ckt; float* Cv; float* Cg;                      // kt, v, gate outputs
    const float* bg;                                       // gate bias
    const float* eb;                                       // edge bias [b,q,k,h]
    float* ps;                                             // exp-sum partials
};

__device__ __forceinline__ unsigned f2tf32(float f) {
    unsigned r;
    asm("cvt.rna.tf32.f32 %0, %1;" : "=r"(r) : "f"(f));
    return r;
}
__device__ __forceinline__ float frnd(float f) { return __uint_as_float(f2tf32(f)); }

__device__ __forceinline__ void cp16(unsigned dst, const void* src, bool pred) {
    int sz = pred ? 16 : 0;
    asm volatile("cp.async.cg.shared.global [%0], [%1], 16, %2;"
                 :: "r"(dst), "l"(src), "r"(sz));
}

__device__ __forceinline__ void ldsm_x4(unsigned* r, unsigned addr) {
    asm volatile("ldmatrix.sync.aligned.m8n8.x4.b16 {%0,%1,%2,%3}, [%4];"
                 : "=r"(r[0]), "=r"(r[1]), "=r"(r[2]), "=r"(r[3]) : "r"(addr));
}

__device__ __forceinline__ void mma_tf32(float* c, const unsigned* a, const unsigned* b) {
    asm volatile(
        "mma.sync.aligned.m16n8k8.row.col.f32.tf32.tf32.f32 "
        "{%0,%1,%2,%3}, {%4,%5,%6,%7}, {%8,%9}, {%0,%1,%2,%3};"
        : "+f"(c[0]), "+f"(c[1]), "+f"(c[2]), "+f"(c[3])
        : "r"(a[0]), "r"(a[1]), "r"(a[2]), "r"(a[3]), "r"(b[0]), "r"(b[1]));
}

// ====== 2-stage cp.async TF32 GEMM, BK=32, ldmatrix A-fragments ============
template<int BN, int EPI, bool ZX, bool PEXP>
__global__ __launch_bounds__(256, 2)
void tgemm(const float* __restrict__ A, const float* __restrict__ B,
           float* __restrict__ C, int M, int N, int K,
           int lda, int ldb, int ldc, int zdiv,
           long long sA1, long long sA2, long long sB1, long long sB2,
           long long sC1, long long sC2,
           const float* __restrict__ bias, const float* __restrict__ res,
           const unsigned char* __restrict__ mask, XArgs xa)
{
    constexpr int BM = 128, BK = 32, AS = BK + 4, BS = BN + 8;
    constexpr int MT = 2;
    constexpr int NT = BN / 16;
    constexpr int WN = BN / 2;

    extern __shared__ float smem[];
    float* As_ = smem;
    float* Bs_ = smem + 2 * BM * AS;

    int z, bn, bm;
    if (ZX) { z = blockIdx.x; bn = blockIdx.y; bm = blockIdx.z; }
    else    { z = blockIdx.z; bn = blockIdx.x; bm = blockIdx.y; }
    int z1 = z / zdiv, z2 = z - z1 * zdiv;
    A += (size_t)z1 * sA1 + (size_t)z2 * sA2;
    size_t coff = (size_t)z1 * sC1 + (size_t)z2 * sC2;

    const float* Bbase = B;
    int bnoff = bn * BN;
    int bsel = 0;
    if (EPI == EPI_PROJ4) {
        bsel = bn >> 3;
        bnoff = (bn & 7) * 128;
        Bbase = (bsel == 0) ? B : (bsel == 1) ? xa.Bw1 : (bsel == 2) ? xa.Bw2 : xa.Bw3;
    } else {
        Bbase += (size_t)z1 * sB1 + (size_t)z2 * sB2;
    }

    int tid = threadIdx.x, lane = tid & 31, wid = tid >> 5;
    int wm = (wid & 3) * 32;
    int wn = (wid >> 2) * WN;

    float sinv = 0.f;
    int xrow = tid >> 1, xc0 = (tid & 1) * 16;
    if (PEXP) {
        int qg = bm * BM + xrow;
        const float* p8 = xa.ps + ((size_t)z * 1024 + qg) * 8;
        float sum = ((p8[0] + p8[1]) + (p8[2] + p8[3]))
                  + ((p8[4] + p8[5]) + (p8[6] + p8[7]));
        sinv = 1.f / sum;
    }

    unsigned as_base = (unsigned)__cvta_generic_to_shared(As_);
    unsigned bs_base = (unsigned)__cvta_generic_to_shared(Bs_);

    // ldmatrix per-thread A address part: row = wm + (lane&15), koff = (lane>>4)*4
    unsigned a_thr_off = (unsigned)(((wm + (lane & 15)) * AS + ((lane >> 4) << 2)) * 4);

    const float* Ag = A + (size_t)(bm * BM) * lda;
    const float* Bg = Bbase + bnoff;

    float acc[MT][NT][4] = {};

    constexpr int ALD = (BM * BK) / (256 * 4);
    constexpr int BLD = (BK * BN) / (256 * 4);

    int KT = K / BK;

    {
#pragma unroll
        for (int i = 0; i < ALD; i++) {
            int f = tid + 256 * i;
            int row = f >> 3, c4 = (f & 7) * 4;
            cp16(as_base + (unsigned)(row * AS + c4) * 4,
                 Ag + (size_t)row * lda + c4, true);
        }
#pragma unroll
        for (int i = 0; i < BLD; i++) {
            int f = tid + 256 * i;
            int row = f / (BN / 4), c4 = (f % (BN / 4)) * 4;
            cp16(bs_base + (unsigned)(row * BS + c4) * 4,
                 Bg + (size_t)row * ldb + c4, (bnoff + c4) < N);
        }
        asm volatile("cp.async.commit_group;");
    }

    for (int kt = 0; kt < KT; kt++) {
        int st = kt & 1;
        if (kt + 1 < KT) {
            int ns = st ^ 1;
            int k0 = (kt + 1) * BK;
#pragma unroll
            for (int i = 0; i < ALD; i++) {
                int f = tid + 256 * i;
                int row = f >> 3, c4 = (f & 7) * 4;
                cp16(as_base + (unsigned)(ns * BM * AS + row * AS + c4) * 4,
                     Ag + (size_t)row * lda + k0 + c4, true);
            }
#pragma unroll
            for (int i = 0; i < BLD; i++) {
                int f = tid + 256 * i;
                int row = f / (BN / 4), c4 = (f % (BN / 4)) * 4;
                cp16(bs_base + (unsigned)(ns * BK * BS + row * BS + c4) * 4,
                     Bg + (size_t)(k0 + row) * ldb + c4, (bnoff + c4) < N);
            }
            asm volatile("cp.async.commit_group;");
            asm volatile("cp.async.wait_group %0;" :: "n"(1));
        } else {
            asm volatile("cp.async.wait_group %0;" :: "n"(0));
        }
        __syncthreads();

        float* Asr = As_ + st * BM * AS;
        const float* Bsr = Bs_ + st * BK * BS;
        unsigned a_st_base = as_base + (unsigned)(st * BM * AS) * 4 + a_thr_off;

        if (PEXP) {
            // s holds exp(score); normalize + RN-round (vectorized)
            float4* b4p = (float4*)(Asr + xrow * AS + xc0);
#pragma unroll
            for (int i = 0; i < 4; i++) {
                float4 t = b4p[i];
                t.x = frnd(t.x * sinv);
                t.y = frnd(t.y * sinv);
                t.z = frnd(t.z * sinv);
                t.w = frnd(t.w * sinv);
                b4p[i] = t;
            }
            __syncthreads();
        }

#pragma unroll
        for (int kk = 0; kk < BK; kk += 8) {
            unsigned a[MT][4], b[NT][2];
#pragma unroll
            for (int m_ = 0; m_ < MT; m_++)
                ldsm_x4(a[m_], a_st_base + (unsigned)((m_ * 16 * AS + kk) * 4));
            int br = kk + (lane & 3), bc = wn + (lane >> 2);
#pragma unroll
            for (int n_ = 0; n_ < NT; n_++) {
                b[n_][0] = __float_as_uint(Bsr[br * BS + bc + n_ * 8]);
                b[n_][1] = __float_as_uint(Bsr[(br + 4) * BS + bc + n_ * 8]);
            }
#pragma unroll
            for (int m_ = 0; m_ < MT; m_++)
#pragma unroll
                for (int n_ = 0; n_ < NT; n_++)
                    mma_tf32(acc[m_][n_], a[m_], b[n_]);
        }
        __syncthreads();
    }

    // epilogue (+ deterministic exp-sum reduction for SCOREBIAS)
    float esum[MT][2];
    if (EPI == EPI_SCOREBIAS) {
#pragma unroll
        for (int m_ = 0; m_ < MT; m_++) { esum[m_][0] = 0.f; esum[m_][1] = 0.f; }
    }
#pragma unroll
    for (int m_ = 0; m_ < MT; m_++) {
#pragma unroll
        for (int n_ = 0; n_ < NT; n_++) {
#pragma unroll
            for (int e = 0; e < 4; e++) {
                int m = bm * BM + wm + m_ * 16 + (lane >> 2) + (e >> 1) * 8;
                int n = bnoff + wn + n_ * 8 + (lane & 3) * 2 + (e & 1);
                if (n >= N) continue;
                float v = acc[m_][n_][e];
                size_t idx = coff + (size_t)m * ldc + n;
                if (EPI == EPI_PROJ4) {
                    if (bsel == 0) {
                        C[idx] = frnd(v * 0.125f);
                    } else if (bsel == 1) {
                        size_t o = (size_t)(m >> 10) * (1u << 20) + (size_t)n * 1024 + (m & 1023);
                        xa.Ckt[o] = frnd(v);
                    } else if (bsel == 2) {
                        xa.Cv[idx] = frnd(v);
                    } else {
                        float zz = v + xa.bg[n];
                        xa.Cg[idx] = 1.f / (1.f + __expf(-zz));
                    }
                } else if (EPI == EPI_SCOREBIAS) {
                    float t = v + xa.eb[((size_t)(z1 * 1024 + m) * 1024 + n) * 16 + z2];
                    if (mask[z1 * 1024 + n]) t = -CUDART_INF_F;
                    float ex = __expf(t);
                    C[idx] = ex;                     // store exp(score)
                    esum[m_][e >> 1] += ex;
                } else if (EPI == EPI_GATE) {
                    C[idx] = frnd(v * res[idx]);
                } else if (EPI == EPI_RESBIAS) {
                    C[idx] = v + bias[n] + res[idx];
                } else if (EPI == EPI_SILU) {
                    float zz = v + bias[n];
                    C[idx] = frnd(zz / (1.f + __expf(-zz)));
                }
            }
        }
    }

    if (EPI == EPI_SCOREBIAS) {
        float* rowsum = As_;              // smem reuse (free after last sync)
        if (tid < 128) rowsum[tid] = 0.f;
        __syncthreads();
#pragma unroll
        for (int m_ = 0; m_ < MT; m_++) {
#pragma unroll
            for (int rh = 0; rh < 2; rh++) {
                float val = esum[m_][rh];
                val += __shfl_xor_sync(0xffffffffu, val, 1);
                val += __shfl_xor_sync(0xffffffffu, val, 2);
                if ((lane & 3) == 0)      // 2 warps contribute per row: deterministic
                    atomicAdd(&rowsum[wm + m_ * 16 + (lane >> 2) + rh * 8], val);
            }
        }
        __syncthreads();
        if (tid < 128)
            xa.ps[((size_t)z * 1024 + bm * BM + tid) * 8 + bn] = rowsum[tid];
    }
}

// ---- RN-round copy (x) ------------------------------------------------------
__global__ __launch_bounds__(256)
void round_copy(const float* __restrict__ in, float* __restrict__ out)
{
    int i = blockIdx.x * 256 + threadIdx.x;
    float4 v = reinterpret_cast<const float4*>(in)[i];
    v.x = frnd(v.x); v.y = frnd(v.y); v.z = frnd(v.z); v.w = frnd(v.w);
    reinterpret_cast<float4*>(out)[i] = v;
}

// ------- attn_out writer: reads exp(s) + partials (no exp) ------------------
__global__ __launch_bounds__(512)
void attn_writer(const float* __restrict__ s, const float* __restrict__ ps,
                 float* __restrict__ attn_out)
{
    int q = blockIdx.x;
    int b = blockIdx.y;
    int w    = threadIdx.x >> 5;
    int lane = threadIdx.x & 31;
    const float* row = s + (((size_t)(b * 16 + w) * 1024 + q)) * 1024;

    const float* p8 = ps + ((size_t)(b * 16 + w) * 1024 + q) * 8;
    float sum = ((p8[0] + p8[1]) + (p8[2] + p8[3]))
              + ((p8[4] + p8[5]) + (p8[6] + p8[7]));
    float inv = 1.f / sum;

    float v[32];
#pragma unroll
    for (int i = 0; i < 32; i++)
        v[i] = row[i * 32 + lane] * inv;

    __shared__ float tile[16 * 513];
    float* out = attn_out + ((size_t)(b * 1024 + q)) * 16384;
#pragma unroll
    for (int half = 0; half < 2; half++) {
        __syncthreads();
#pragma unroll
        for (int i = 0; i < 16; i++) {
            int k = (half * 16 + i) * 32 + lane;
            tile[w * 513 + (k - half * 512)] = v[half * 16 + i];
        }
        __syncthreads();
        for (int idx = threadIdx.x; idx < 8192; idx += 512) {
            int k = idx >> 4, h = idx & 15;
            out[half * 8192 + idx] = tile[h * 513 + k];
        }
    }
}

// ---------------- row LayerNorm over D=1024 --------------------------------
template<bool RND>
__global__ __launch_bounds__(256)
void ln_kernel(const float* __restrict__ in, float* __restrict__ out,
               const float* __restrict__ gg, const float* __restrict__ bb)
{
    int row = blockIdx.x;
    int tid = threadIdx.x;
    float4 v = reinterpret_cast<const float4*>(in + (size_t)row * 1024)[tid];
    float s  = v.x + v.y + v.z + v.w;
    float ss = v.x * v.x + v.y * v.y + v.z * v.z + v.w * v.w;
#pragma unroll
    for (int o = 16; o; o >>= 1) {
        s  += __shfl_xor_sync(0xffffffffu, s, o);
        ss += __shfl_xor_sync(0xffffffffu, ss, o);
    }
    __shared__ float rs[8], rss[8];
    if ((tid & 31) == 0) { rs[tid >> 5] = s; rss[tid >> 5] = ss; }
    __syncthreads();
    if (tid < 32) {
        float a = (tid < 8) ? rs[tid] : 0.f;
        float c = (tid < 8) ? rss[tid] : 0.f;
#pragma unroll
        for (int o = 4; o; o >>= 1) {
            a += __shfl_xor_sync(0xffffffffu, a, o);
            c += __shfl_xor_sync(0xffffffffu, c, o);
        }
        if (tid == 0) { rs[0] = a; rss[0] = c; }
    }
    __syncthreads();
    float mean = rs[0] * (1.f / 1024.f);
    float var  = rss[0] * (1.f / 1024.f) - mean * mean;
    float inv  = rsqrtf(var + 1e-5f);
    float4 g4 = ((const float4*)gg)[tid];
    float4 b4 = ((const float4*)bb)[tid];
    float4 o4;
    o4.x = (v.x - mean) * inv * g4.x + b4.x;
    o4.y = (v.y - mean) * inv * g4.y + b4.y;
    o4.z = (v.z - mean) * inv * g4.z + b4.z;
    o4.w = (v.w - mean) * inv * g4.w + b4.w;
    if (RND) { o4.x = frnd(o4.x); o4.y = frnd(o4.y); o4.z = frnd(o4.z); o4.w = frnd(o4.w); }
    reinterpret_cast<float4*>(out + (size_t)row * 1024)[tid] = o4;
}

// ---------------- launcher --------------------------------------------------
extern "C" void kernel_launch(void* const* d_in, const int* in_sizes, int n_in,
                              void* d_out, int out_size)
{
    const float* x    = (const float*)d_in[0];
    const float* eb   = (const float*)d_in[1];
    const unsigned char* mask = (const unsigned char*)d_in[2];
    const float* wq   = (const float*)d_in[3];
    const float* wk   = (const float*)d_in[4];
    const float* wv   = (const float*)d_in[5];
    const float* wo   = (const float*)d_in[6];
    const float* bo   = (const float*)d_in[7];
    const float* wg   = (const float*)d_in[8];
    const float* bg   = (const float*)d_in[9];
    const float* w1   = (const float*)d_in[10];
    const float* b1   = (const float*)d_in[11];
    const float* w2   = (const float*)d_in[12];
    const float* b2   = (const float*)d_in[13];
    const float* ln1g = (const float*)d_in[14];
    const float* ln1b = (const float*)d_in[15];
    const float* ln2g = (const float*)d_in[16];
    const float* ln2b = (const float*)d_in[17];

    float* out_x    = (float*)d_out;
    float* out_attn = (float*)d_out + (size_t)NTOK * 1024;

    float *xr, *q, *kt, *v, *g, *s, *ps, *o, *r1, *y, *u, *r2;
    cudaGetSymbolAddress((void**)&xr,  g_xr);
    cudaGetSymbolAddress((void**)&q,   g_q);
    cudaGetSymbolAddress((void**)&kt,  g_kt);
    cudaGetSymbolAddress((void**)&v,   g_v);
    cudaGetSymbolAddress((void**)&g,   g_gate);
    cudaGetSymbolAddress((void**)&s,   g_s);
    cudaGetSymbolAddress((void**)&ps,  g_ps);
    cudaGetSymbolAddress((void**)&o,   g_o);
    cudaGetSymbolAddress((void**)&r1,  g_r1);
    cudaGetSymbolAddress((void**)&y,   g_y);
    cudaGetSymbolAddress((void**)&u,   g_u);
    cudaGetSymbolAddress((void**)&r2,  g_r2);

    const int SM128 = (2 * (128 * 36 + 32 * 136)) * 4;  // 71680
    const int SM64  = (2 * (128 * 36 + 32 * 72)) * 4;   // 55296
    cudaFuncSetAttribute(tgemm<128, EPI_PROJ4, false, false>,
                         cudaFuncAttributeMaxDynamicSharedMemorySize, SM128);
    cudaFuncSetAttribute(tgemm<128, EPI_SCOREBIAS, true, false>,
                         cudaFuncAttributeMaxDynamicSharedMemorySize, SM128);
    cudaFuncSetAttribute(tgemm<64, EPI_GATE, true, true>,
                         cudaFuncAttributeMaxDynamicSharedMemorySize, SM64);
    cudaFuncSetAttribute(tgemm<128, EPI_RESBIAS, false, false>,
                         cudaFuncAttributeMaxDynamicSharedMemorySize, SM128);
    cudaFuncSetAttribute(tgemm<128, EPI_SILU, false, false>,
                         cudaFuncAttributeMaxDynamicSharedMemorySize, SM128);

    XArgs xa{};
    xa.bg = bg; xa.eb = eb; xa.ps = ps;

    // 0) RN-round x
    round_copy<<<2048, 256>>>(x, xr);

    // 1) fused projections
    {
        XArgs pa = xa;
        pa.Bw1 = wk; pa.Bw2 = wv; pa.Bw3 = wg;
        pa.Ckt = kt; pa.Cv = v;  pa.Cg = g;
        tgemm<128, EPI_PROJ4, false, false><<<dim3(32, 16, 1), 256, SM128>>>(
            xr, wq, q, NTOK, 1024, 1024, 1024, 1024, 1024,
            1, 0, 0, 0, 0, 0, 0, nullptr, nullptr, nullptr, pa);
    }

    // 2) scores -> exp(scores) in s; epilogue emits exp-sum partials
    tgemm<128, EPI_SCOREBIAS, true, false><<<dim3(32, 8, 8), 256, SM128>>>(
        q, kt, s, 1024, 1024, 64, 1024, 1024, 1024,
        16,
        (long long)1048576, 64,
        (long long)1048576, 65536,
        (long long)16777216, 1048576,
        nullptr, nullptr, mask, xa);

    // 3) o = (probs @ V_h) * gate — transform: mul by sinv only
    tgemm<64, EPI_GATE, true, true><<<dim3(32, 1, 8), 256, SM64>>>(
        s, v, o, 1024, 64, 1024, 1024, 1024, 1024,
        16,
        (long long)16777216, 1048576,
        (long long)1048576, 64,
        (long long)1048576, 64,
        nullptr, g, nullptr, xa);

    // 4) r1 = o @ wo + bo + x ; LN1 -> y
    tgemm<128, EPI_RESBIAS, false, false><<<dim3(8, 16, 1), 256, SM128>>>(
        o, wo, r1, NTOK, 1024, 1024, 1024, 1024, 1024,
        1, 0, 0, 0, 0, 0, 0, bo, x, nullptr, xa);
    ln_kernel<true><<<NTOK, 256>>>(r1, y, ln1g, ln1b);

    // 5) FFN
    tgemm<128, EPI_SILU, false, false><<<dim3(16, 16, 1), 256, SM128>>>(
        y, w1, u, NTOK, FFN, 1024, 1024, FFN, FFN,
        1, 0, 0, 0, 0, 0, 0, b1, nullptr, nullptr, xa);
    tgemm<128, EPI_RESBIAS, false, false><<<dim3(8, 16, 1), 256, SM128>>>(
        u, w2, r2, NTOK, 1024, FFN, FFN, 1024, 1024,
        1, 0, 0, 0, 0, 0, 0, b2, y, nullptr, xa);
    ln_kernel<false><<<NTOK, 256>>>(r2, out_x, ln2g, ln2b);

    // 6) attn_out writer (reads exp(s) + partials)
    attn_writer<<<dim3(1024, 2), 512>>>(s, ps, out_attn);
}

// round 17
// speedup vs baseline: 1.2742x; 1.0023x over previous
#include <cuda_runtime.h>
#include <cuda_fp16.h>
#include <math_constants.h>

#define NTOK  2048
#define FFN   2048

// ---------------- scratch ----------------
__device__ float  g_xr  [NTOK * 1024];
__device__ float  g_q   [NTOK * 1024];
__device__ float  g_kt  [2 * 1024 * 1024];
__device__ float  g_v   [NTOK * 1024];
__device__ float  g_gate[NTOK * 1024];
__device__ __half g_s   [(size_t)2 * 16 * 1024 * 1024];  // exp(scores), fp16
__device__ float  g_ps  [32 * 1024 * 8];                 // exp-sum partials
__device__ float  g_o   [NTOK * 1024];
__device__ float  g_r1  [NTOK * 1024];
__device__ float  g_y   [NTOK * 1024];
__device__ float  g_u   [NTOK * FFN];
__device__ float  g_r2  [NTOK * 1024];

enum { EPI_PROJ4 = 0, EPI_SCOREBIAS = 1, EPI_RESBIAS = 3, EPI_SILU = 4 };

struct XArgs {
    const float* Bw1; const float* Bw2; const float* Bw3;  // wk, wv, wg
    float* Ckt; float* Cv; float* Cg;                      // kt, v, gate outputs
    const float* bg;                                       // gate bias
    const float* eb;                                       // edge bias [b,q,k,h]
    float* ps;                                             // exp-sum partials
};

__device__ __forceinline__ unsigned f2tf32(float f) {
    unsigned r;
    asm("cvt.rna.tf32.f32 %0, %1;" : "=r"(r) : "f"(f));
    return r;
}
__device__ __forceinline__ float frnd(float f) { return __uint_as_float(f2tf32(f)); }

__device__ __forceinline__ void cp16(unsigned dst, const void* src, bool pred) {
    int sz = pred ? 16 : 0;
    asm volatile("cp.async.cg.shared.global [%0], [%1], 16, %2;"
                 :: "r"(dst), "l"(src), "r"(sz));
}

__device__ __forceinline__ void ldsm_x4(unsigned* r, unsigned addr) {
    asm volatile("ldmatrix.sync.aligned.m8n8.x4.b16 {%0,%1,%2,%3}, [%4];"
                 : "=r"(r[0]), "=r"(r[1]), "=r"(r[2]), "=r"(r[3]) : "r"(addr));
}

__device__ __forceinline__ void mma_tf32(float* c, const unsigned* a, const unsigned* b) {
    asm volatile(
        "mma.sync.aligned.m16n8k8.row.col.f32.tf32.tf32.f32 "
        "{%0,%1,%2,%3}, {%4,%5,%6,%7}, {%8,%9}, {%0,%1,%2,%3};"
        : "+f"(c[0]), "+f"(c[1]), "+f"(c[2]), "+f"(c[3])
        : "r"(a[0]), "r"(a[1]), "r"(a[2]), "r"(a[3]), "r"(b[0]), "r"(b[1]));
}

// ====== generic 2-stage cp.async TF32 GEMM (R16), ldmatrix A ===============
template<int BN, int EPI, bool ZX>
__global__ __launch_bounds__(256, 2)
void tgemm(const float* __restrict__ A, const float* __restrict__ B,
           float* __restrict__ C, int M, int N, int K,
           int lda, int ldb, int ldc, int zdiv,
           long long sA1, long long sA2, long long sB1, long long sB2,
           long long sC1, long long sC2,
           const float* __restrict__ bias, const float* __restrict__ res,
           const unsigned char* __restrict__ mask, XArgs xa)
{
    constexpr int BM = 128, BK = 32, AS = BK + 4, BS = BN + 8;
    constexpr int MT = 2;
    constexpr int NT = BN / 16;
    constexpr int WN = BN / 2;

    extern __shared__ float smem[];
    float* As_ = smem;
    float* Bs_ = smem + 2 * BM * AS;

    int z, bn, bm;
    if (ZX) { z = blockIdx.x; bn = blockIdx.y; bm = blockIdx.z; }
    else    { z = blockIdx.z; bn = blockIdx.x; bm = blockIdx.y; }
    int z1 = z / zdiv, z2 = z - z1 * zdiv;
    A += (size_t)z1 * sA1 + (size_t)z2 * sA2;
    size_t coff = (size_t)z1 * sC1 + (size_t)z2 * sC2;

    const float* Bbase = B;
    int bnoff = bn * BN;
    int bsel = 0;
    if (EPI == EPI_PROJ4) {
        bsel = bn >> 3;
        bnoff = (bn & 7) * 128;
        Bbase = (bsel == 0) ? B : (bsel == 1) ? xa.Bw1 : (bsel == 2) ? xa.Bw2 : xa.Bw3;
    } else {
        Bbase += (size_t)z1 * sB1 + (size_t)z2 * sB2;
    }

    int tid = threadIdx.x, lane = tid & 31, wid = tid >> 5;
    int wm = (wid & 3) * 32;
    int wn = (wid >> 2) * WN;

    unsigned as_base = (unsigned)__cvta_generic_to_shared(As_);
    unsigned bs_base = (unsigned)__cvta_generic_to_shared(Bs_);
    unsigned a_thr_off = (unsigned)(((wm + (lane & 15)) * AS + ((lane >> 4) << 2)) * 4);

    const float* Ag = A + (size_t)(bm * BM) * lda;
    const float* Bg = Bbase + bnoff;

    float acc[MT][NT][4] = {};

    constexpr int ALD = (BM * BK) / (256 * 4);
    constexpr int BLD = (BK * BN) / (256 * 4);

    int KT = K / BK;

    {
#pragma unroll
        for (int i = 0; i < ALD; i++) {
            int f = tid + 256 * i;
            int row = f >> 3, c4 = (f & 7) * 4;
            cp16(as_base + (unsigned)(row * AS + c4) * 4,
                 Ag + (size_t)row * lda + c4, true);
        }
#pragma unroll
        for (int i = 0; i < BLD; i++) {
            int f = tid + 256 * i;
            int row = f / (BN / 4), c4 = (f % (BN / 4)) * 4;
            cp16(bs_base + (unsigned)(row * BS + c4) * 4,
                 Bg + (size_t)row * ldb + c4, (bnoff + c4) < N);
        }
        asm volatile("cp.async.commit_group;");
    }

    for (int kt = 0; kt < KT; kt++) {
        int st = kt & 1;
        if (kt + 1 < KT) {
            int ns = st ^ 1;
            int k0 = (kt + 1) * BK;
#pragma unroll
            for (int i = 0; i < ALD; i++) {
                int f = tid + 256 * i;
                int row = f >> 3, c4 = (f & 7) * 4;
                cp16(as_base + (unsigned)(ns * BM * AS + row * AS + c4) * 4,
                     Ag + (size_t)row * lda + k0 + c4, true);
            }
#pragma unroll
            for (int i = 0; i < BLD; i++) {
                int f = tid + 256 * i;
                int row = f / (BN / 4), c4 = (f % (BN / 4)) * 4;
                cp16(bs_base + (unsigned)(ns * BK * BS + row * BS + c4) * 4,
                     Bg + (size_t)(k0 + row) * ldb + c4, (bnoff + c4) < N);
            }
            asm volatile("cp.async.commit_group;");
            asm volatile("cp.async.wait_group %0;" :: "n"(1));
        } else {
            asm volatile("cp.async.wait_group %0;" :: "n"(0));
        }
        __syncthreads();

        const float* Bsr = Bs_ + st * BK * BS;
        unsigned a_st_base = as_base + (unsigned)(st * BM * AS) * 4 + a_thr_off;

#pragma unroll
        for (int kk = 0; kk < BK; kk += 8) {
            unsigned a[MT][4], b[NT][2];
#pragma unroll
            for (int m_ = 0; m_ < MT; m_++)
                ldsm_x4(a[m_], a_st_base + (unsigned)((m_ * 16 * AS + kk) * 4));
            int br = kk + (lane & 3), bc = wn + (lane >> 2);
#pragma unroll
            for (int n_ = 0; n_ < NT; n_++) {
                b[n_][0] = __float_as_uint(Bsr[br * BS + bc + n_ * 8]);
                b[n_][1] = __float_as_uint(Bsr[(br + 4) * BS + bc + n_ * 8]);
            }
#pragma unroll
            for (int m_ = 0; m_ < MT; m_++)
#pragma unroll
                for (int n_ = 0; n_ < NT; n_++)
                    mma_tf32(acc[m_][n_], a[m_], b[n_]);
        }
        __syncthreads();
    }

    // epilogue (+ deterministic exp-sum reduction for SCOREBIAS)
    float esum[MT][2];
    if (EPI == EPI_SCOREBIAS) {
#pragma unroll
        for (int m_ = 0; m_ < MT; m_++) { esum[m_][0] = 0.f; esum[m_][1] = 0.f; }
    }
#pragma unroll
    for (int m_ = 0; m_ < MT; m_++) {
#pragma unroll
        for (int n_ = 0; n_ < NT; n_++) {
#pragma unroll
            for (int e = 0; e < 4; e++) {
                int m = bm * BM + wm + m_ * 16 + (lane >> 2) + (e >> 1) * 8;
                int n = bnoff + wn + n_ * 8 + (lane & 3) * 2 + (e & 1);
                if (n >= N) continue;
                float v = acc[m_][n_][e];
                size_t idx = coff + (size_t)m * ldc + n;
                if (EPI == EPI_PROJ4) {
                    if (bsel == 0) {
                        C[idx] = frnd(v * 0.125f);
                    } else if (bsel == 1) {
                        size_t o = (size_t)(m >> 10) * (1u << 20) + (size_t)n * 1024 + (m & 1023);
                        xa.Ckt[o] = frnd(v);
                    } else if (bsel == 2) {
                        xa.Cv[idx] = frnd(v);
                    } else {
                        float zz = v + xa.bg[n];
                        xa.Cg[idx] = 1.f / (1.f + __expf(-zz));
                    }
                } else if (EPI == EPI_SCOREBIAS) {
                    float t = v + xa.eb[((size_t)(z1 * 1024 + m) * 1024 + n) * 16 + z2];
                    if (mask[z1 * 1024 + n]) t = -CUDART_INF_F;
                    float ex = __expf(t);
                    ((__half*)C)[idx] = __float2half(ex);   // fp16 exp(score)
                    esum[m_][e >> 1] += ex;
                } else if (EPI == EPI_RESBIAS) {
                    C[idx] = v + bias[n] + res[idx];
                } else if (EPI == EPI_SILU) {
                    float zz = v + bias[n];
                    C[idx] = frnd(zz / (1.f + __expf(-zz)));
                }
            }
        }
    }

    if (EPI == EPI_SCOREBIAS) {
        float* rowsum = As_;
        if (tid < 128) rowsum[tid] = 0.f;
        __syncthreads();
#pragma unroll
        for (int m_ = 0; m_ < MT; m_++) {
#pragma unroll
            for (int rh = 0; rh < 2; rh++) {
                float val = esum[m_][rh];
                val += __shfl_xor_sync(0xffffffffu, val, 1);
                val += __shfl_xor_sync(0xffffffffu, val, 2);
                if ((lane & 3) == 0)
                    atomicAdd(&rowsum[wm + m_ * 16 + (lane >> 2) + rh * 8], val);
            }
        }
        __syncthreads();
        if (tid < 128)
            xa.ps[((size_t)z * 1024 + bm * BM + tid) * 8 + bn] = rowsum[tid];
    }
}

// ====== dedicated AV GEMM: half probs (staged+converted) @ float V =========
__global__ __launch_bounds__(256, 2)
void tgemm_av(const __half* __restrict__ S, const float* __restrict__ V,
              float* __restrict__ O, const float* __restrict__ gate,
              const float* __restrict__ ps)
{
    constexpr int BM = 128, BN = 64, BK = 32;
    constexpr int HS = 40;           // half staging row stride (80B, 16B mult)
    constexpr int AS = 36;           // float compute row stride
    constexpr int BS = 72;
    constexpr int MT = 2, NT = 4, WN = 32;

    extern __shared__ char dyn[];
    __half* Hs  = (__half*)dyn;                         // [2][BM*HS]  20480B
    float*  Asf = (float*)(dyn + 2 * BM * HS * 2);      // [BM*AS]     18432B
    float*  Bs_ = (float*)(dyn + 2 * BM * HS * 2 + BM * AS * 4); // [2][BK*BS]

    int z = blockIdx.x, bm = blockIdx.z;
    int z1 = z >> 4, z2 = z & 15;

    const __half* Ag = S + (size_t)z1 * 16777216 + (size_t)z2 * 1048576
                         + (size_t)(bm * BM) * 1024;
    const float*  Bg = V + (size_t)z1 * 1048576 + z2 * 64;
    size_t coff = (size_t)z1 * 1048576 + z2 * 64;

    int tid = threadIdx.x, lane = tid & 31, wid = tid >> 5;
    int wm = (wid & 3) * 32;
    int wn = (wid >> 2) * WN;

    int xrow = tid >> 1, xc0 = (tid & 1) * 16;
    int qg = bm * BM + xrow;
    const float* p8 = ps + ((size_t)z * 1024 + qg) * 8;
    float sum = ((p8[0] + p8[1]) + (p8[2] + p8[3]))
              + ((p8[4] + p8[5]) + (p8[6] + p8[7]));
    float sinv = 1.f / sum;

    unsigned hs_base = (unsigned)__cvta_generic_to_shared(Hs);
    unsigned bs_base = (unsigned)__cvta_generic_to_shared(Bs_);
    unsigned as_base = (unsigned)__cvta_generic_to_shared(Asf);
    unsigned a_thr_off = (unsigned)(((wm + (lane & 15)) * AS + ((lane >> 4) << 2)) * 4);

    float acc[MT][NT][4] = {};

    // A(half): 128 rows x 4 chunks(8 halfs) = 512 / 256thr = 2 passes
    // B(float): 32 rows x 16 chunks(4 floats) = 512 / 256 = 2 passes
    {
#pragma unroll
        for (int i = 0; i < 2; i++) {
            int f = tid + 256 * i;
            int row = f >> 2, c8 = (f & 3) * 8;
            cp16(hs_base + (unsigned)(row * HS + c8) * 2,
                 Ag + (size_t)row * 1024 + c8, true);
        }
#pragma unroll
        for (int i = 0; i < 2; i++) {
            int f = tid + 256 * i;
            int row = f >> 4, c4 = (f & 15) * 4;
            cp16(bs_base + (unsigned)(row * BS + c4) * 4,
                 Bg + (size_t)row * 1024 + c4, true);
        }
        asm volatile("cp.async.commit_group;");
    }

    for (int kt = 0; kt < 32; kt++) {
        int st = kt & 1;
        if (kt + 1 < 32) {
            int ns = st ^ 1;
            int k0 = (kt + 1) * BK;
#pragma unroll
            for (int i = 0; i < 2; i++) {
                int f = tid + 256 * i;
                int row = f >> 2, c8 = (f & 3) * 8;
                cp16(hs_base + (unsigned)(ns * BM * HS + row * HS + c8) * 2,
                     Ag + (size_t)row * 1024 + k0 + c8, true);
            }
#pragma unroll
            for (int i = 0; i < 2; i++) {
                int f = tid + 256 * i;
                int row = f >> 4, c4 = (f & 15) * 4;
                cp16(bs_base + (unsigned)(ns * BK * BS + row * BS + c4) * 4,
                     Bg + (size_t)(k0 + row) * 1024 + c4, true);
            }
            asm volatile("cp.async.commit_group;");
            asm volatile("cp.async.wait_group %0;" :: "n"(1));
        } else {
            asm volatile("cp.async.wait_group %0;" :: "n"(0));
        }
        __syncthreads();

        // convert half probs -> normalized tf32-rounded floats in Asf
        {
            const uint4* hp = (const uint4*)(Hs + st * BM * HS + xrow * HS + xc0);
            uint4 u0 = hp[0], u1 = hp[1];
            float4* fp = (float4*)(Asf + xrow * AS + xc0);
            float2 f0 = __half22float2(*(__half2*)&u0.x);
            float2 f1 = __half22float2(*(__half2*)&u0.y);
            float2 f2 = __half22float2(*(__half2*)&u0.z);
            float2 f3 = __half22float2(*(__half2*)&u0.w);
            float2 f4 = __half22float2(*(__half2*)&u1.x);
            float2 f5 = __half22float2(*(__half2*)&u1.y);
            float2 f6 = __half22float2(*(__half2*)&u1.z);
            float2 f7 = __half22float2(*(__half2*)&u1.w);
            float4 o0 = { frnd(f0.x * sinv), frnd(f0.y * sinv), frnd(f1.x * sinv), frnd(f1.y * sinv) };
            float4 o1 = { frnd(f2.x * sinv), frnd(f2.y * sinv), frnd(f3.x * sinv), frnd(f3.y * sinv) };
            float4 o2 = { frnd(f4.x * sinv), frnd(f4.y * sinv), frnd(f5.x * sinv), frnd(f5.y * sinv) };
            float4 o3 = { frnd(f6.x * sinv), frnd(f6.y * sinv), frnd(f7.x * sinv), frnd(f7.y * sinv) };
            fp[0] = o0; fp[1] = o1; fp[2] = o2; fp[3] = o3;
        }
        __syncthreads();

        const float* Bsr = Bs_ + st * BK * BS;
        unsigned a_st_base = as_base + a_thr_off;
#pragma unroll
        for (int kk = 0; kk < BK; kk += 8) {
            unsigned a[MT][4], b[NT][2];
#pragma unroll
            for (int m_ = 0; m_ < MT; m_++)
                ldsm_x4(a[m_], a_st_base + (unsigned)((m_ * 16 * AS + kk) * 4));
            int br = kk + (lane & 3), bc = wn + (lane >> 2);
#pragma unroll
            for (int n_ = 0; n_ < NT; n_++) {
                b[n_][0] = __float_as_uint(Bsr[br * BS + bc + n_ * 8]);
                b[n_][1] = __float_as_uint(Bsr[(br + 4) * BS + bc + n_ * 8]);
            }
#pragma unroll
            for (int m_ = 0; m_ < MT; m_++)
#pragma unroll
                for (int n_ = 0; n_ < NT; n_++)
                    mma_tf32(acc[m_][n_], a[m_], b[n_]);
        }
        __syncthreads();
    }

    // epilogue: gated output
#pragma unroll
    for (int m_ = 0; m_ < MT; m_++) {
#pragma unroll
        for (int n_ = 0; n_ < NT; n_++) {
#pragma unroll
            for (int e = 0; e < 4; e++) {
                int m = bm * BM + wm + m_ * 16 + (lane >> 2) + (e >> 1) * 8;
                int n = wn + n_ * 8 + (lane & 3) * 2 + (e & 1);
                size_t idx = coff + (size_t)m * 1024 + n;
                O[idx] = frnd(acc[m_][n_][e] * gate[idx]);
            }
        }
    }
}

// ---- RN-round copy (x) ------------------------------------------------------
__global__ __launch_bounds__(256)
void round_copy(const float* __restrict__ in, float* __restrict__ out)
{
    int i = blockIdx.x * 256 + threadIdx.x;
    float4 v = reinterpret_cast<const float4*>(in)[i];
    v.x = frnd(v.x); v.y = frnd(v.y); v.z = frnd(v.z); v.w = frnd(v.w);
    reinterpret_cast<float4*>(out)[i] = v;
}

// ------- attn_out writer: reads half exp(s) + partials ----------------------
__global__ __launch_bounds__(512)
void attn_writer(const __half* __restrict__ s, const float* __restrict__ ps,
                 float* __restrict__ attn_out)
{
    int q = blockIdx.x;
    int b = blockIdx.y;
    int w    = threadIdx.x >> 5;
    int lane = threadIdx.x & 31;
    const __half* row = s + (((size_t)(b * 16 + w) * 1024 + q)) * 1024;

    const float* p8 = ps + ((size_t)(b * 16 + w) * 1024 + q) * 8;
    float sum = ((p8[0] + p8[1]) + (p8[2] + p8[3]))
              + ((p8[4] + p8[5]) + (p8[6] + p8[7]));
    float inv = 1.f / sum;

    float v[32];
#pragma unroll
    for (int i = 0; i < 32; i++)
        v[i] = __half2float(row[i * 32 + lane]) * inv;

    __shared__ float tile[16 * 513];
    float* out = attn_out + ((size_t)(b * 1024 + q)) * 16384;
#pragma unroll
    for (int half_ = 0; half_ < 2; half_++) {
        __syncthreads();
#pragma unroll
        for (int i = 0; i < 16; i++) {
            int k = (half_ * 16 + i) * 32 + lane;
            tile[w * 513 + (k - half_ * 512)] = v[half_ * 16 + i];
        }
        __syncthreads();
        for (int idx = threadIdx.x; idx < 8192; idx += 512) {
            int k = idx >> 4, h = idx & 15;
            out[half_ * 8192 + idx] = tile[h * 513 + k];
        }
    }
}

// ---------------- row LayerNorm over D=1024 --------------------------------
template<bool RND>
__global__ __launch_bounds__(256)
void ln_kernel(const float* __restrict__ in, float* __restrict__ out,
               const float* __restrict__ gg, const float* __restrict__ bb)
{
    int row = blockIdx.x;
    int tid = threadIdx.x;
    float4 v = reinterpret_cast<const float4*>(in + (size_t)row * 1024)[tid];
    float s  = v.x + v.y + v.z + v.w;
    float ss = v.x * v.x + v.y * v.y + v.z * v.z + v.w * v.w;
#pragma unroll
    for (int o = 16; o; o >>= 1) {
        s  += __shfl_xor_sync(0xffffffffu, s, o);
        ss += __shfl_xor_sync(0xffffffffu, ss, o);
    }
    __shared__ float rs[8], rss[8];
    if ((tid & 31) == 0) { rs[tid >> 5] = s; rss[tid >> 5] = ss; }
    __syncthreads();
    if (tid < 32) {
        float a = (tid < 8) ? rs[tid] : 0.f;
        float c = (tid < 8) ? rss[tid] : 0.f;
#pragma unroll
        for (int o = 4; o; o >>= 1) {
            a += __shfl_xor_sync(0xffffffffu, a, o);
            c += __shfl_xor_sync(0xffffffffu, c, o);
        }
        if (tid == 0) { rs[0] = a; rss[0] = c; }
    }
    __syncthreads();
    float mean = rs[0] * (1.f / 1024.f);
    float var  = rss[0] * (1.f / 1024.f) - mean * mean;
    float inv  = rsqrtf(var + 1e-5f);
    float4 g4 = ((const float4*)gg)[tid];
    float4 b4 = ((const float4*)bb)[tid];
    float4 o4;
    o4.x = (v.x - mean) * inv * g4.x + b4.x;
    o4.y = (v.y - mean) * inv * g4.y + b4.y;
    o4.z = (v.z - mean) * inv * g4.z + b4.z;
    o4.w = (v.w - mean) * inv * g4.w + b4.w;
    if (RND) { o4.x = frnd(o4.x); o4.y = frnd(o4.y); o4.z = frnd(o4.z); o4.w = frnd(o4.w); }
    reinterpret_cast<float4*>(out + (size_t)row * 1024)[tid] = o4;
}

// ---------------- launcher --------------------------------------------------
extern "C" void kernel_launch(void* const* d_in, const int* in_sizes, int n_in,
                              void* d_out, int out_size)
{
    const float* x    = (const float*)d_in[0];
    const float* eb   = (const float*)d_in[1];
    const unsigned char* mask = (const unsigned char*)d_in[2];
    const float* wq   = (const float*)d_in[3];
    const float* wk   = (const float*)d_in[4];
    const float* wv   = (const float*)d_in[5];
    const float* wo   = (const float*)d_in[6];
    const float* bo   = (const float*)d_in[7];
    const float* wg   = (const float*)d_in[8];
    const float* bg   = (const float*)d_in[9];
    const float* w1   = (const float*)d_in[10];
    const float* b1   = (const float*)d_in[11];
    const float* w2   = (const float*)d_in[12];
    const float* b2   = (const float*)d_in[13];
    const float* ln1g = (const float*)d_in[14];
    const float* ln1b = (const float*)d_in[15];
    const float* ln2g = (const float*)d_in[16];
    const float* ln2b = (const float*)d_in[17];

    float* out_x    = (float*)d_out;
    float* out_attn = (float*)d_out + (size_t)NTOK * 1024;

    float *xr, *q, *kt, *v, *g, *ps, *o, *r1, *y, *u, *r2;
    __half* s;
    cudaGetSymbolAddress((void**)&xr,  g_xr);
    cudaGetSymbolAddress((void**)&q,   g_q);
    cudaGetSymbolAddress((void**)&kt,  g_kt);
    cudaGetSymbolAddress((void**)&v,   g_v);
    cudaGetSymbolAddress((void**)&g,   g_gate);
    cudaGetSymbolAddress((void**)&s,   g_s);
    cudaGetSymbolAddress((void**)&ps,  g_ps);
    cudaGetSymbolAddress((void**)&o,   g_o);
    cudaGetSymbolAddress((void**)&r1,  g_r1);
    cudaGetSymbolAddress((void**)&y,   g_y);
    cudaGetSymbolAddress((void**)&u,   g_u);
    cudaGetSymbolAddress((void**)&r2,  g_r2);

    const int SM128 = (2 * (128 * 36 + 32 * 136)) * 4;              // 71680
    const int SMAV  = 2 * 128 * 40 * 2 + 128 * 36 * 4 + 2 * 32 * 72 * 4; // 57344
    cudaFuncSetAttribute(tgemm<128, EPI_PROJ4, false>,
                         cudaFuncAttributeMaxDynamicSharedMemorySize, SM128);
    cudaFuncSetAttribute(tgemm<128, EPI_SCOREBIAS, true>,
                         cudaFuncAttributeMaxDynamicSharedMemorySize, SM128);
    cudaFuncSetAttribute(tgemm_av,
                         cudaFuncAttributeMaxDynamicSharedMemorySize, SMAV);
    cudaFuncSetAttribute(tgemm<128, EPI_RESBIAS, false>,
                         cudaFuncAttributeMaxDynamicSharedMemorySize, SM128);
    cudaFuncSetAttribute(tgemm<128, EPI_SILU, false>,
                         cudaFuncAttributeMaxDynamicSharedMemorySize, SM128);

    XArgs xa{};
    xa.bg = bg; xa.eb = eb; xa.ps = ps;

    // 0) RN-round x
    round_copy<<<2048, 256>>>(x, xr);

    // 1) fused projections
    {
        XArgs pa = xa;
        pa.Bw1 = wk; pa.Bw2 = wv; pa.Bw3 = wg;
        pa.Ckt = kt; pa.Cv = v;  pa.Cg = g;
        tgemm<128, EPI_PROJ4, false><<<dim3(32, 16, 1), 256, SM128>>>(
            xr, wq, q, NTOK, 1024, 1024, 1024, 1024, 1024,
            1, 0, 0, 0, 0, 0, 0, nullptr, nullptr, nullptr, pa);
    }

    // 2) scores -> fp16 exp(scores) in s; epilogue emits exp-sum partials
    tgemm<128, EPI_SCOREBIAS, true><<<dim3(32, 8, 8), 256, SM128>>>(
        q, kt, (float*)s, 1024, 1024, 64, 1024, 1024, 1024,
        16,
        (long long)1048576, 64,
        (long long)1048576, 65536,
        (long long)16777216, 1048576,
        nullptr, nullptr, mask, xa);

    // 3) o = (probs @ V_h) * gate  (dedicated half-prob AV kernel)
    tgemm_av<<<dim3(32, 1, 8), 256, SMAV>>>(s, v, o, g, ps);

    // 4) r1 = o @ wo + bo + x ; LN1 -> y
    tgemm<128, EPI_RESBIAS, false><<<dim3(8, 16, 1), 256, SM128>>>(
        o, wo, r1, NTOK, 1024, 1024, 1024, 1024, 1024,
        1, 0, 0, 0, 0, 0, 0, bo, x, nullptr, xa);
    ln_kernel<true><<<NTOK, 256>>>(r1, y, ln1g, ln1b);

    // 5) FFN
    tgemm<128, EPI_SILU, false><<<dim3(16, 16, 1), 256, SM128>>>(
        y, w1, u, NTOK, FFN, 1024, 1024, FFN, FFN,
        1, 0, 0, 0, 0, 0, 0, b1, nullptr, nullptr, xa);
    tgemm<128, EPI_RESBIAS, false><<<dim3(8, 16, 1), 256, SM128>>>(
        u, w2, r2, NTOK, 1024, FFN, FFN, 1024, 1024,
        1, 0, 0, 0, 0, 0, 0, b2, y, nullptr, xa);
    ln_kernel<false><<<NTOK, 256>>>(r2, out_x, ln2g, ln2b);

    // 6) attn_out writer (reads fp16 exp(s) + partials)
    attn_writer<<<dim3(1024, 2), 512>>>(s, ps, out_attn);
}